// round 1
// baseline (speedup 1.0000x reference)
#include <cuda_runtime.h>
#include <cuda_bf16.h>
#include <math.h>

// Problem constants
#define TT 256
#define BB 256
#define FF 128
#define HH 1024

// Tiling
#define TBJ 32   // j (hidden unit) tile
#define TBB 32   // batch tile
#define KC  32   // K chunk

// Persistent device state (allocation-free scratch)
__device__ float g_h0[2][BB * HH];
__device__ float g_h1[2][BB * HH];
__device__ float g_c0[BB * HH];
__device__ float g_c1[BB * HH];
__device__ float g_h1_first[BB * HH];

__device__ __forceinline__ float sigmoidf_(float x) {
    return 1.0f / (1.0f + expf(-x));
}

__global__ void zero_state_kernel() {
    int i = blockIdx.x * blockDim.x + threadIdx.x;
    if (i < BB * HH) {
        g_h0[0][i] = 0.0f;
        g_h1[0][i] = 0.0f;
        g_c0[i] = 0.0f;
        g_c1[i] = 0.0f;
    }
}

// Fused LSTM step: gates = bias + in @ W_ih^T + h_in @ W_hh^T, then cell update.
// Each thread owns 4 batch rows x 1 hidden unit j, accumulating all 4 gates
// (rows j, H+j, 2H+j, 3H+j of the weight matrices) so the cell update is local.
template <int K_IN>
__global__ __launch_bounds__(256, 2) void lstm_step_kernel(
    const float* __restrict__ in,    // (B, K_IN)
    const float* __restrict__ h_in,  // (B, H)
    const float* __restrict__ W_ih,  // (4H, K_IN)
    const float* __restrict__ W_hh,  // (4H, H)
    const float* __restrict__ b_ih,  // (4H)
    const float* __restrict__ b_hh,  // (4H)
    float* __restrict__ c_state,     // (B, H), in-place
    float* __restrict__ h_out,       // (B, H)
    float* __restrict__ h_save)      // optional copy of h_out (t==0 of layer 1)
{
    __shared__ float w_s[4 * TBJ][KC + 4];   // 128 x 36
    __shared__ float in_s[TBB][KC + 4];      // 32 x 36

    const int tid = threadIdx.x;
    const int tj  = tid & 31;
    const int tb  = tid >> 5;                // 0..7, each owns 4 batch rows
    const int j0  = blockIdx.x * TBJ;
    const int b0  = blockIdx.y * TBB;
    const int j   = j0 + tj;

    float acc[4][4];                         // [gate][b_sub]
#pragma unroll
    for (int g = 0; g < 4; g++) {
        const float bsum = b_ih[g * HH + j] + b_hh[g * HH + j];
#pragma unroll
        for (int bs = 0; bs < 4; bs++) acc[g][bs] = bsum;
    }

    constexpr int NCHUNK = (K_IN + HH) / KC;

    for (int ch = 0; ch < NCHUNK; ch++) {
        int kbase = ch * KC;
        const float* wsrc;
        const float* isrc;
        int ld;
        if (kbase < K_IN) {
            wsrc = W_ih; isrc = in; ld = K_IN;
        } else {
            wsrc = W_hh; isrc = h_in; ld = HH; kbase -= K_IN;
        }

        __syncthreads();  // protect previous iteration's reads

        // Load W tile: 128 rows x 32 cols = 1024 float4, 4 per thread
#pragma unroll
        for (int i = 0; i < 4; i++) {
            int lin = tid + i * 256;
            int row = lin >> 3;   // 0..127
            int q   = lin & 7;
            int g   = row >> 5;
            int jr  = row & 31;
            float4 v = *(const float4*)&wsrc[(size_t)(g * HH + j0 + jr) * ld + kbase + q * 4];
            *(float4*)&w_s[row][q * 4] = v;
        }
        // Load activation tile: 32 rows x 32 cols = 256 float4, 1 per thread
        {
            int row = tid >> 3;
            int q   = tid & 7;
            float4 v = *(const float4*)&isrc[(size_t)(b0 + row) * ld + kbase + q * 4];
            *(float4*)&in_s[row][q * 4] = v;
        }
        __syncthreads();

#pragma unroll
        for (int k4 = 0; k4 < 8; k4++) {
            float4 w0 = *(const float4*)&w_s[0 * 32 + tj][k4 * 4];
            float4 w1 = *(const float4*)&w_s[1 * 32 + tj][k4 * 4];
            float4 w2 = *(const float4*)&w_s[2 * 32 + tj][k4 * 4];
            float4 w3 = *(const float4*)&w_s[3 * 32 + tj][k4 * 4];
#pragma unroll
            for (int bs = 0; bs < 4; bs++) {
                float4 xv = *(const float4*)&in_s[tb * 4 + bs][k4 * 4];
                acc[0][bs] += w0.x * xv.x; acc[0][bs] += w0.y * xv.y;
                acc[0][bs] += w0.z * xv.z; acc[0][bs] += w0.w * xv.w;
                acc[1][bs] += w1.x * xv.x; acc[1][bs] += w1.y * xv.y;
                acc[1][bs] += w1.z * xv.z; acc[1][bs] += w1.w * xv.w;
                acc[2][bs] += w2.x * xv.x; acc[2][bs] += w2.y * xv.y;
                acc[2][bs] += w2.z * xv.z; acc[2][bs] += w2.w * xv.w;
                acc[3][bs] += w3.x * xv.x; acc[3][bs] += w3.y * xv.y;
                acc[3][bs] += w3.z * xv.z; acc[3][bs] += w3.w * xv.w;
            }
        }
    }

    // LSTM cell update (PyTorch gate order i, f, g, o)
#pragma unroll
    for (int bs = 0; bs < 4; bs++) {
        const int b = b0 + tb * 4 + bs;
        const size_t idx = (size_t)b * HH + j;
        float ig = sigmoidf_(acc[0][bs]);
        float fg = sigmoidf_(acc[1][bs]);
        float gg = tanhf(acc[2][bs]);
        float og = sigmoidf_(acc[3][bs]);
        float cp = c_state[idx];
        float cn = fg * cp + ig * gg;
        float hn = og * tanhf(cn);
        c_state[idx] = cn;
        h_out[idx] = hn;
        if (h_save) h_save[idx] = hn;
    }
}

// y[b][f] = b_lin[f] + sum_k h1_first[b][k] * W_lin[f][k]
__global__ void linear_kernel(const float* __restrict__ hin,
                              const float* __restrict__ W_lin,  // (F, H)
                              const float* __restrict__ b_lin,
                              float* __restrict__ y) {
    __shared__ float hrow[HH];
    const int b = blockIdx.x;
    for (int i = threadIdx.x; i < HH; i += blockDim.x)
        hrow[i] = hin[(size_t)b * HH + i];
    __syncthreads();
    const int f = threadIdx.x;
    float acc = b_lin[f];
    const float* w = &W_lin[(size_t)f * HH];
#pragma unroll 4
    for (int k = 0; k < HH; k++) acc += hrow[k] * w[k];
    y[(size_t)b * FF + f] = acc;
}

// Pack h_n = [h0_T, h1_T], c_n = [c0_T, c1_T] after y in the output buffer.
__global__ void write_states_kernel(float* __restrict__ out) {
    int i = blockIdx.x * blockDim.x + threadIdx.x;
    if (i >= BB * HH) return;
    const int YO = BB * FF;                      // 32768
    out[YO + i]              = g_h0[0][i];       // final h buffers end in slot 0
    out[YO + BB * HH + i]    = g_h1[0][i];
    out[YO + 2 * BB * HH + i] = g_c0[i];
    out[YO + 3 * BB * HH + i] = g_c1[i];
}

extern "C" void kernel_launch(void* const* d_in, const int* in_sizes, int n_in,
                              void* d_out, int out_size) {
    (void)in_sizes; (void)n_in; (void)out_size;
    const float* x     = (const float*)d_in[0];
    const float* W_ih0 = (const float*)d_in[1];
    const float* W_hh0 = (const float*)d_in[2];
    const float* b_ih0 = (const float*)d_in[3];
    const float* b_hh0 = (const float*)d_in[4];
    const float* W_ih1 = (const float*)d_in[5];
    const float* W_hh1 = (const float*)d_in[6];
    const float* b_ih1 = (const float*)d_in[7];
    const float* b_hh1 = (const float*)d_in[8];
    const float* W_lin = (const float*)d_in[9];
    const float* b_lin = (const float*)d_in[10];
    float* out = (float*)d_out;

    void* p;
    float *ph0, *ph1, *pc0, *pc1, *pfirst;
    cudaGetSymbolAddress(&p, g_h0);       ph0    = (float*)p;
    cudaGetSymbolAddress(&p, g_h1);       ph1    = (float*)p;
    cudaGetSymbolAddress(&p, g_c0);       pc0    = (float*)p;
    cudaGetSymbolAddress(&p, g_c1);       pc1    = (float*)p;
    cudaGetSymbolAddress(&p, g_h1_first); pfirst = (float*)p;

    zero_state_kernel<<<(BB * HH + 255) / 256, 256>>>();

    const dim3 grid(HH / TBJ, BB / TBB);  // (32, 8)

    for (int t = 0; t < TT; t++) {
        float* h0_in  = ph0 + (t & 1) * BB * HH;
        float* h0_out = ph0 + ((t + 1) & 1) * BB * HH;
        float* h1_in  = ph1 + (t & 1) * BB * HH;
        float* h1_out = ph1 + ((t + 1) & 1) * BB * HH;

        lstm_step_kernel<FF><<<grid, 256>>>(
            x + (size_t)t * BB * FF, h0_in, W_ih0, W_hh0, b_ih0, b_hh0,
            pc0, h0_out, nullptr);

        lstm_step_kernel<HH><<<grid, 256>>>(
            h0_out, h1_in, W_ih1, W_hh1, b_ih1, b_hh1,
            pc1, h1_out, (t == 0) ? pfirst : nullptr);
    }

    linear_kernel<<<BB, FF>>>(pfirst, W_lin, b_lin, out);
    write_states_kernel<<<(BB * HH + 255) / 256, 256>>>(out);
}

// round 3
// speedup vs baseline: 2.8293x; 2.8293x over previous
#include <cuda_runtime.h>
#include <math.h>
#include <stdint.h>

// ---------------- problem constants ----------------
#define TT 256
#define BB 256
#define FF 128
#define HH 1024

// ---------------- tiling ----------------
#define KC      32
#define CTA_M   64
#define CTA_N   128
#define STAGES  4
#define STRIDE  36                      // smem row stride in floats (conflict-free)
#define A_BYTES (CTA_M * STRIDE * 4)    // 9216
#define W_BYTES (CTA_N * STRIDE * 4)    // 18432
#define STAGE_BYTES (A_BYTES + W_BYTES) // 27648
#define SMEM_BYTES  (STAGES * STAGE_BYTES)
#define ACC_STRIDE 132

// ---------------- persistent device state ----------------
__device__ float g_h0[2][BB * HH];
__device__ float g_h1[2][BB * HH];
__device__ float g_c0[BB * HH];
__device__ float g_c1[BB * HH];
__device__ float g_h1_first[BB * HH];
// tf32-rounded operand copies
__device__ float g_x[TT * BB * FF];
__device__ float g_Wih0[4 * HH * FF];
__device__ float g_Whh0[4 * HH * HH];
__device__ float g_Wih1[4 * HH * HH];
__device__ float g_Whh1[4 * HH * HH];

// ---------------- helpers ----------------
__device__ __forceinline__ uint32_t s2u(const void* p) {
    uint32_t a;
    asm("{ .reg .u64 t; cvta.to.shared.u64 t, %1; cvt.u32.u64 %0, t; }"
        : "=r"(a) : "l"(p));
    return a;
}

__device__ __forceinline__ void cp16(uint32_t s, const float* g) {
    asm volatile("cp.async.cg.shared.global [%0], [%1], 16;" :: "r"(s), "l"(g));
}
#define CP_COMMIT() asm volatile("cp.async.commit_group;" ::: "memory")
#define CP_WAIT(N)  asm volatile("cp.async.wait_group %0;" :: "n"(N) : "memory")

__device__ __forceinline__ float to_tf32(float x) {
    uint32_t r;
    asm("cvt.rna.tf32.f32 %0, %1;" : "=r"(r) : "f"(x));
    return __uint_as_float(r);
}

__device__ __forceinline__ void mma8(float* c, const uint32_t* a, uint32_t b0, uint32_t b1) {
    asm volatile(
        "mma.sync.aligned.m16n8k8.row.col.f32.tf32.tf32.f32 "
        "{%0,%1,%2,%3}, {%4,%5,%6,%7}, {%8,%9}, {%0,%1,%2,%3};"
        : "+f"(c[0]), "+f"(c[1]), "+f"(c[2]), "+f"(c[3])
        : "r"(a[0]), "r"(a[1]), "r"(a[2]), "r"(a[3]), "r"(b0), "r"(b1));
}

__device__ __forceinline__ float sigmoidf_(float x) { return 1.0f / (1.0f + expf(-x)); }

// ---------------- setup kernels ----------------
__global__ void zero_state_kernel() {
    int i = blockIdx.x * blockDim.x + threadIdx.x;
    if (i < BB * HH) {
        g_h0[0][i] = 0.0f;
        g_h1[0][i] = 0.0f;
        g_c0[i] = 0.0f;
        g_c1[i] = 0.0f;
    }
}

__global__ void prep_tf32_kernel(const float* __restrict__ in, float* __restrict__ out, int n) {
    int i = blockIdx.x * blockDim.x + threadIdx.x;
    if (i < n) out[i] = to_tf32(in[i]);
}

// ---------------- fused LSTM step (mma.sync tf32) ----------------
// grid 128: blockIdx.x = m(0..3) + 4*nt(0..31). CTA: M=64 batch x N=128 (gate*32+u).
// Warp w owns the full M=64 and N columns [32w, 32w+32) (one gate); epilogue
// stages accums through SMEM to give each thread all 4 gates of a (b,u).
__device__ __forceinline__ void load_chunk128(
    uint32_t dstA, uint32_t dstW, int tid,
    const float* __restrict__ aSrc, int ald,
    const float* __restrict__ wSrc, int wld, int j0)
{
#pragma unroll
    for (int i = 0; i < 4; i++) {            // A: 64x32 = 512 float4
        int q = tid + i * 128;
        int row = q >> 3, c4 = q & 7;
        cp16(dstA + row * (STRIDE * 4) + c4 * 16, aSrc + (size_t)row * ald + c4 * 4);
    }
#pragma unroll
    for (int i = 0; i < 8; i++) {            // W: 128x32 = 1024 float4
        int q = tid + i * 128;
        int row = q >> 3, c4 = q & 7;
        int g = row >> 5, u = row & 31;
        cp16(dstW + row * (STRIDE * 4) + c4 * 16,
             wSrc + (size_t)(g * HH + j0 + u) * wld + c4 * 4);
    }
    CP_COMMIT();
}

template <int K_IN>
__global__ __launch_bounds__(128) void lstm_step_mma(
    const float* __restrict__ in,    // (B, K_IN) tf32-rounded
    const float* __restrict__ h_in,  // (B, H)    tf32-rounded
    const float* __restrict__ W_ih,  // (4H, K_IN) tf32-rounded
    const float* __restrict__ W_hh,  // (4H, H)    tf32-rounded
    const float* __restrict__ b_ih,
    const float* __restrict__ b_hh,
    float* __restrict__ c_st,        // (B, H) fp32, in-place
    float* __restrict__ h_out,       // (B, H)
    float* __restrict__ h_save)
{
    constexpr int NC    = (K_IN + HH) / KC;
    constexpr int SPLIT = K_IN / KC;

    extern __shared__ float sm[];
    __shared__ float bias_s[CTA_N];

    const int tid  = threadIdx.x;
    const int w    = tid >> 5;
    const int lane = tid & 31;
    const int r4   = lane >> 2, cl = lane & 3;
    const int m    = blockIdx.x & 3;
    const int nt   = blockIdx.x >> 2;
    const int b0   = m * CTA_M;
    const int j0   = nt * 32;

    const uint32_t smb = s2u(sm);

    if (tid < CTA_N) {
        int g = tid >> 5, u = tid & 31;
        bias_s[tid] = b_ih[g * HH + j0 + u] + b_hh[g * HH + j0 + u];
    }

    float acc[4][4][4];
#pragma unroll
    for (int mi = 0; mi < 4; mi++)
#pragma unroll
        for (int ni = 0; ni < 4; ni++)
#pragma unroll
            for (int q = 0; q < 4; q++) acc[mi][ni][q] = 0.0f;

    auto src_for = [&](int ch, const float*& as, int& ald, const float*& ws, int& wld) {
        if (ch < SPLIT) {
            as = in + (size_t)b0 * K_IN + ch * KC; ald = K_IN;
            ws = W_ih + ch * KC;                   wld = K_IN;
        } else {
            int ko = (ch - SPLIT) * KC;
            as = h_in + (size_t)b0 * HH + ko; ald = HH;
            ws = W_hh + ko;                   wld = HH;
        }
    };

    // prologue: 3 stages in flight
#pragma unroll
    for (int s = 0; s < 3; s++) {
        const float* as; const float* ws; int ald, wld;
        src_for(s, as, ald, ws, wld);
        load_chunk128(smb + s * STAGE_BYTES, smb + s * STAGE_BYTES + A_BYTES,
                      tid, as, ald, ws, wld, j0);
    }

#pragma unroll 1
    for (int ch = 0; ch < NC; ch++) {
        if (ch >= NC - 1)      { CP_WAIT(0); }
        else if (ch == NC - 2) { CP_WAIT(1); }
        else                   { CP_WAIT(2); }
        __syncthreads();

        if (ch + 3 < NC) {
            const float* as; const float* ws; int ald, wld;
            src_for(ch + 3, as, ald, ws, wld);
            int buf = (ch + 3) & 3;
            load_chunk128(smb + buf * STAGE_BYTES, smb + buf * STAGE_BYTES + A_BYTES,
                          tid, as, ald, ws, wld, j0);
        }

        const float* As = sm + ((ch & 3) * STAGE_BYTES) / 4;
        const float* Ws = As + A_BYTES / 4;

#pragma unroll
        for (int ks = 0; ks < 4; ks++) {
            const int kk = ks * 8;
            uint32_t a[4][4];
#pragma unroll
            for (int mi = 0; mi < 4; mi++) {
                int R = mi * 16 + r4;
                a[mi][0] = __float_as_uint(As[R * STRIDE + kk + cl]);
                a[mi][1] = __float_as_uint(As[(R + 8) * STRIDE + kk + cl]);
                a[mi][2] = __float_as_uint(As[R * STRIDE + kk + cl + 4]);
                a[mi][3] = __float_as_uint(As[(R + 8) * STRIDE + kk + cl + 4]);
            }
#pragma unroll
            for (int ni = 0; ni < 4; ni++) {
                int n = w * 32 + ni * 8 + r4;
                uint32_t b0r = __float_as_uint(Ws[n * STRIDE + kk + cl]);
                uint32_t b1r = __float_as_uint(Ws[n * STRIDE + kk + cl + 4]);
#pragma unroll
                for (int mi = 0; mi < 4; mi++) mma8(acc[mi][ni], a[mi], b0r, b1r);
            }
        }
    }

    // stage accums to SMEM so each thread can gather all 4 gates of a (b,u)
    __syncthreads();
    float* Acc = sm;
#pragma unroll
    for (int mi = 0; mi < 4; mi++)
#pragma unroll
        for (int ni = 0; ni < 4; ni++) {
            int R   = mi * 16 + r4;
            int col = w * 32 + ni * 8 + 2 * cl;
            *(float2*)&Acc[R * ACC_STRIDE + col]       = make_float2(acc[mi][ni][0], acc[mi][ni][1]);
            *(float2*)&Acc[(R + 8) * ACC_STRIDE + col] = make_float2(acc[mi][ni][2], acc[mi][ni][3]);
        }
    __syncthreads();

    const int u  = tid & 31;
    const int rb = tid >> 5;
#pragma unroll
    for (int rr = 0; rr < 16; rr++) {
        int r = rb * 16 + rr;
        float iv = Acc[r * ACC_STRIDE + u]       + bias_s[u];
        float fv = Acc[r * ACC_STRIDE + 32 + u]  + bias_s[32 + u];
        float gv = Acc[r * ACC_STRIDE + 64 + u]  + bias_s[64 + u];
        float ov = Acc[r * ACC_STRIDE + 96 + u]  + bias_s[96 + u];
        float ig = sigmoidf_(iv);
        float fg = sigmoidf_(fv);
        float gg = tanhf(gv);
        float og = sigmoidf_(ov);
        size_t idx = (size_t)(b0 + r) * HH + j0 + u;
        float cn = fg * c_st[idx] + ig * gg;
        c_st[idx] = cn;
        float hn = og * tanhf(cn);
        float hq = to_tf32(hn);   // keep next-step GEMM operand rna-rounded
        h_out[idx] = hq;
        if (h_save) h_save[idx] = hq;
    }
}

// ---------------- head + output packing ----------------
__global__ void linear_kernel(const float* __restrict__ hin,
                              const float* __restrict__ W_lin,
                              const float* __restrict__ b_lin,
                              float* __restrict__ y) {
    __shared__ float hrow[HH];
    const int b = blockIdx.x;
    for (int i = threadIdx.x; i < HH; i += blockDim.x)
        hrow[i] = hin[(size_t)b * HH + i];
    __syncthreads();
    const int f = threadIdx.x;
    float acc = b_lin[f];
    const float* wv = &W_lin[(size_t)f * HH];
#pragma unroll 4
    for (int k = 0; k < HH; k++) acc += hrow[k] * wv[k];
    y[(size_t)b * FF + f] = acc;
}

__global__ void write_states_kernel(float* __restrict__ out) {
    int i = blockIdx.x * blockDim.x + threadIdx.x;
    if (i >= BB * HH) return;
    const int YO = BB * FF;
    out[YO + i]               = g_h0[0][i];
    out[YO + BB * HH + i]     = g_h1[0][i];
    out[YO + 2 * BB * HH + i] = g_c0[i];
    out[YO + 3 * BB * HH + i] = g_c1[i];
}

extern "C" void kernel_launch(void* const* d_in, const int* in_sizes, int n_in,
                              void* d_out, int out_size) {
    (void)in_sizes; (void)n_in; (void)out_size;
    const float* x     = (const float*)d_in[0];
    const float* W_ih0 = (const float*)d_in[1];
    const float* W_hh0 = (const float*)d_in[2];
    const float* b_ih0 = (const float*)d_in[3];
    const float* b_hh0 = (const float*)d_in[4];
    const float* W_ih1 = (const float*)d_in[5];
    const float* W_hh1 = (const float*)d_in[6];
    const float* b_ih1 = (const float*)d_in[7];
    const float* b_hh1 = (const float*)d_in[8];
    const float* W_lin = (const float*)d_in[9];
    const float* b_lin = (const float*)d_in[10];
    float* out = (float*)d_out;

    cudaFuncSetAttribute(lstm_step_mma<FF>, cudaFuncAttributeMaxDynamicSharedMemorySize, SMEM_BYTES);
    cudaFuncSetAttribute(lstm_step_mma<HH>, cudaFuncAttributeMaxDynamicSharedMemorySize, SMEM_BYTES);

    void* p;
    float *ph0, *ph1, *pc0, *pc1, *pfirst, *px, *pWih0, *pWhh0, *pWih1, *pWhh1;
    cudaGetSymbolAddress(&p, g_h0);       ph0    = (float*)p;
    cudaGetSymbolAddress(&p, g_h1);       ph1    = (float*)p;
    cudaGetSymbolAddress(&p, g_c0);       pc0    = (float*)p;
    cudaGetSymbolAddress(&p, g_c1);       pc1    = (float*)p;
    cudaGetSymbolAddress(&p, g_h1_first); pfirst = (float*)p;
    cudaGetSymbolAddress(&p, g_x);        px     = (float*)p;
    cudaGetSymbolAddress(&p, g_Wih0);     pWih0  = (float*)p;
    cudaGetSymbolAddress(&p, g_Whh0);     pWhh0  = (float*)p;
    cudaGetSymbolAddress(&p, g_Wih1);     pWih1  = (float*)p;
    cudaGetSymbolAddress(&p, g_Whh1);     pWhh1  = (float*)p;

    zero_state_kernel<<<(BB * HH + 255) / 256, 256>>>();

    // one-time tf32 rounding of GEMM operands
    auto prep = [&](const float* src, float* dst, int n) {
        prep_tf32_kernel<<<(n + 255) / 256, 256>>>(src, dst, n);
    };
    prep(x,     px,    TT * BB * FF);
    prep(W_ih0, pWih0, 4 * HH * FF);
    prep(W_hh0, pWhh0, 4 * HH * HH);
    prep(W_ih1, pWih1, 4 * HH * HH);
    prep(W_hh1, pWhh1, 4 * HH * HH);

    const dim3 grid(128);   // 4 M-tiles x 32 unit-tiles
    const dim3 blk(128);

    for (int t = 0; t < TT; t++) {
        float* h0_in  = ph0 + (t & 1) * BB * HH;
        float* h0_out = ph0 + ((t + 1) & 1) * BB * HH;
        float* h1_in  = ph1 + (t & 1) * BB * HH;
        float* h1_out = ph1 + ((t + 1) & 1) * BB * HH;

        lstm_step_mma<FF><<<grid, blk, SMEM_BYTES>>>(
            px + (size_t)t * BB * FF, h0_in, pWih0, pWhh0, b_ih0, b_hh0,
            pc0, h0_out, nullptr);

        lstm_step_mma<HH><<<grid, blk, SMEM_BYTES>>>(
            h0_out, h1_in, pWih1, pWhh1, b_ih1, b_hh1,
            pc1, h1_out, (t == 0) ? pfirst : nullptr);
    }

    linear_kernel<<<BB, FF>>>(pfirst, W_lin, b_lin, out);
    write_states_kernel<<<(BB * HH + 255) / 256, 256>>>(out);
}

// round 4
// speedup vs baseline: 3.6693x; 1.2969x over previous
#include <cuda_runtime.h>
#include <math.h>
#include <stdint.h>

// ---------------- problem constants ----------------
#define TT 256
#define BB 256
#define FF 128
#define HH 1024

// ---------------- tiling ----------------
#define KC      32
#define CTA_M   64
#define CTA_N   128
#define STAGES  4
#define STRIDE  36                        // smem row stride (floats), conflict-free
#define A_BYTES (CTA_M * STRIDE * 4)      // 9216
#define W_BYTES (CTA_N * STRIDE * 4)      // 18432
#define STAGE_BYTES (A_BYTES + W_BYTES)   // 27648
#define SMEM_BYTES  (STAGES * STAGE_BYTES)// 110592
#define ACC_STRIDE 132

// ---------------- persistent device state ----------------
__device__ float g_h0[2][BB * HH];
__device__ float g_h1[2][BB * HH];
__device__ float g_c0[BB * HH];
__device__ float g_c1[BB * HH];
__device__ float g_h1_first[BB * HH];
// tf32-rounded operand copies
__device__ float g_x[TT * BB * FF];
__device__ float g_Wih0[4 * HH * FF];
__device__ float g_Whh0[4 * HH * HH];
__device__ float g_Wih1[4 * HH * HH];
__device__ float g_Whh1[4 * HH * HH];

// ---------------- helpers ----------------
__device__ __forceinline__ uint32_t s2u(const void* p) {
    uint32_t a;
    asm("{ .reg .u64 t; cvta.to.shared.u64 t, %1; cvt.u32.u64 %0, t; }"
        : "=r"(a) : "l"(p));
    return a;
}

__device__ __forceinline__ void cp16(uint32_t s, const float* g) {
    asm volatile("cp.async.cg.shared.global [%0], [%1], 16;" :: "r"(s), "l"(g));
}
#define CP_COMMIT() asm volatile("cp.async.commit_group;" ::: "memory")
#define CP_WAIT(N)  asm volatile("cp.async.wait_group %0;" :: "n"(N) : "memory")

__device__ __forceinline__ float to_tf32(float x) {
    uint32_t r;
    asm("cvt.rna.tf32.f32 %0, %1;" : "=r"(r) : "f"(x));
    return __uint_as_float(r);
}

__device__ __forceinline__ void ldsm4(uint32_t* r, uint32_t addr) {
    asm volatile("ldmatrix.sync.aligned.m8n8.x4.shared.b16 {%0,%1,%2,%3}, [%4];"
        : "=r"(r[0]), "=r"(r[1]), "=r"(r[2]), "=r"(r[3]) : "r"(addr));
}

__device__ __forceinline__ void mma8(float* c, const uint32_t* a, uint32_t b0, uint32_t b1) {
    asm volatile(
        "mma.sync.aligned.m16n8k8.row.col.f32.tf32.tf32.f32 "
        "{%0,%1,%2,%3}, {%4,%5,%6,%7}, {%8,%9}, {%0,%1,%2,%3};"
        : "+f"(c[0]), "+f"(c[1]), "+f"(c[2]), "+f"(c[3])
        : "r"(a[0]), "r"(a[1]), "r"(a[2]), "r"(a[3]), "r"(b0), "r"(b1));
}

__device__ __forceinline__ float sigmoidf_(float x) { return 1.0f / (1.0f + expf(-x)); }

// ---------------- setup kernels ----------------
__global__ void zero_state_kernel() {
    int i = blockIdx.x * blockDim.x + threadIdx.x;
    if (i < BB * HH) {
        g_h0[0][i] = 0.0f;
        g_h1[0][i] = 0.0f;
        g_c0[i] = 0.0f;
        g_c1[i] = 0.0f;
    }
}

__global__ void prep_tf32_kernel(const float* __restrict__ in, float* __restrict__ out, int n) {
    int i = blockIdx.x * blockDim.x + threadIdx.x;
    if (i < n) out[i] = to_tf32(in[i]);
}

// ---------------- chunk loader (256 threads) ----------------
__device__ __forceinline__ void load_chunk256(
    uint32_t dstA, uint32_t dstW, int tid,
    const float* __restrict__ aSrc, int ald,
    const float* __restrict__ wSrc, int wld, int j0)
{
#pragma unroll
    for (int i = 0; i < 2; i++) {            // A: 64x32 = 512 float4
        int q = tid + i * 256;
        int row = q >> 3, c4 = q & 7;
        cp16(dstA + row * (STRIDE * 4) + c4 * 16, aSrc + (size_t)row * ald + c4 * 4);
    }
#pragma unroll
    for (int i = 0; i < 4; i++) {            // W: 128x32 = 1024 float4
        int q = tid + i * 256;
        int row = q >> 3, c4 = q & 7;
        int g = row >> 5, u = row & 31;
        cp16(dstW + row * (STRIDE * 4) + c4 * 16,
             wSrc + (size_t)(g * HH + j0 + u) * wld + c4 * 4);
    }
    CP_COMMIT();
}

// ---------------- fused LSTM step body (mma.sync tf32, ldmatrix) ----------------
// bid 0..127 = m(0..3) + 4*nt(0..31). CTA: M=64 batch x N=128 (= 4 gates x 32 units).
// 8 warps as 2(m) x 4(n); warp tile 32x32 (mi 0..1, ni 0..3, warp wn owns gate wn).
template <int K_IN>
__device__ __forceinline__ void lstm_body(
    int bid, float* sm, float* bias_s,
    const float* __restrict__ in,    // (B, K_IN) tf32-rounded
    const float* __restrict__ h_in,  // (B, H)    tf32-rounded
    const float* __restrict__ W_ih,  // (4H, K_IN) tf32-rounded
    const float* __restrict__ W_hh,  // (4H, H)    tf32-rounded
    const float* __restrict__ b_ih,
    const float* __restrict__ b_hh,
    float* __restrict__ c_st,        // (B, H) fp32, in-place
    float* __restrict__ h_out,       // (B, H)
    float* __restrict__ h_save)
{
    constexpr int NC    = (K_IN + HH) / KC;
    constexpr int SPLIT = K_IN / KC;

    const int tid  = threadIdx.x;
    const int w    = tid >> 5;
    const int lane = tid & 31;
    const int wm   = w & 1;          // M half
    const int wn   = w >> 1;         // gate / N block
    const int r4   = lane >> 2, cl = lane & 3;
    const int m    = bid & 3;
    const int nt   = bid >> 2;
    const int b0   = m * CTA_M;
    const int j0   = nt * 32;

    const uint32_t smb = s2u(sm);

    if (tid < CTA_N) {
        int g = tid >> 5, u = tid & 31;
        bias_s[tid] = b_ih[g * HH + j0 + u] + b_hh[g * HH + j0 + u];
    }

    // ldmatrix per-lane byte offsets (within a stage buffer)
    const int arow = (lane & 7) + ((lane >> 3) & 1) * 8;
    const int acb  = ((lane >> 4) & 1) * 16;
    const uint32_t aoff0 = (uint32_t)((wm * 32 + 0 * 16 + arow) * (STRIDE * 4) + acb);
    const uint32_t aoff1 = (uint32_t)((wm * 32 + 1 * 16 + arow) * (STRIDE * 4) + acb);
    const uint32_t boff  = (uint32_t)((wn * 32 + (lane >> 3) * 8 + (lane & 7)) * (STRIDE * 4));

    float acc[2][4][4];
#pragma unroll
    for (int mi = 0; mi < 2; mi++)
#pragma unroll
        for (int ni = 0; ni < 4; ni++)
#pragma unroll
            for (int q = 0; q < 4; q++) acc[mi][ni][q] = 0.0f;

    auto src_for = [&](int ch, const float*& as, int& ald, const float*& ws, int& wld) {
        if (ch < SPLIT) {
            as = in + (size_t)b0 * K_IN + ch * KC; ald = K_IN;
            ws = W_ih + ch * KC;                   wld = K_IN;
        } else {
            int ko = (ch - SPLIT) * KC;
            as = h_in + (size_t)b0 * HH + ko; ald = HH;
            ws = W_hh + ko;                   wld = HH;
        }
    };

#pragma unroll
    for (int s = 0; s < 3; s++) {
        const float* as; const float* ws; int ald, wld;
        src_for(s, as, ald, ws, wld);
        load_chunk256(smb + s * STAGE_BYTES, smb + s * STAGE_BYTES + A_BYTES,
                      tid, as, ald, ws, wld, j0);
    }

#pragma unroll 1
    for (int ch = 0; ch < NC; ch++) {
        if (ch >= NC - 1)      { CP_WAIT(0); }
        else if (ch == NC - 2) { CP_WAIT(1); }
        else                   { CP_WAIT(2); }
        __syncthreads();

        if (ch + 3 < NC) {
            const float* as; const float* ws; int ald, wld;
            src_for(ch + 3, as, ald, ws, wld);
            int buf = (ch + 3) & 3;
            load_chunk256(smb + buf * STAGE_BYTES, smb + buf * STAGE_BYTES + A_BYTES,
                          tid, as, ald, ws, wld, j0);
        }

        const uint32_t aBase = smb + (ch & 3) * STAGE_BYTES;
        const uint32_t wBase = aBase + A_BYTES;

#pragma unroll
        for (int ks = 0; ks < 4; ks++) {
            uint32_t a0[4], a1[4], br0[4], br1[4];
            ldsm4(a0,  aBase + aoff0 + ks * 32);
            ldsm4(a1,  aBase + aoff1 + ks * 32);
            ldsm4(br0, wBase + boff + ks * 32);
            ldsm4(br1, wBase + boff + ks * 32 + 16);
#pragma unroll
            for (int ni = 0; ni < 4; ni++) {
                mma8(acc[0][ni], a0, br0[ni], br1[ni]);
                mma8(acc[1][ni], a1, br0[ni], br1[ni]);
            }
        }
    }

    // stage accums through SMEM so each thread gathers all 4 gates of a (b,u)
    __syncthreads();
    float* Acc = sm;
#pragma unroll
    for (int mi = 0; mi < 2; mi++)
#pragma unroll
        for (int ni = 0; ni < 4; ni++) {
            int R   = wm * 32 + mi * 16 + r4;
            int col = wn * 32 + ni * 8 + 2 * cl;
            *(float2*)&Acc[R * ACC_STRIDE + col]       = make_float2(acc[mi][ni][0], acc[mi][ni][1]);
            *(float2*)&Acc[(R + 8) * ACC_STRIDE + col] = make_float2(acc[mi][ni][2], acc[mi][ni][3]);
        }
    __syncthreads();

    const int u  = tid & 31;
    const int rb = tid >> 5;
#pragma unroll
    for (int rr = 0; rr < 8; rr++) {
        int r = rb * 8 + rr;
        float iv = Acc[r * ACC_STRIDE + u]      + bias_s[u];
        float fv = Acc[r * ACC_STRIDE + 32 + u] + bias_s[32 + u];
        float gv = Acc[r * ACC_STRIDE + 64 + u] + bias_s[64 + u];
        float ov = Acc[r * ACC_STRIDE + 96 + u] + bias_s[96 + u];
        float ig = sigmoidf_(iv);
        float fg = sigmoidf_(fv);
        float gg = tanhf(gv);
        float og = sigmoidf_(ov);
        size_t idx = (size_t)(b0 + r) * HH + j0 + u;
        float cn = fg * c_st[idx] + ig * gg;
        c_st[idx] = cn;
        float hn = og * tanhf(cn);
        float hq = to_tf32(hn);
        h_out[idx] = hq;
        if (h_save) h_save[idx] = hq;
    }
}

// standalone single-layer step (grid 128)
template <int K_IN>
__global__ __launch_bounds__(256, 2) void lstm_step_one(
    const float* __restrict__ in, const float* __restrict__ h_in,
    const float* __restrict__ W_ih, const float* __restrict__ W_hh,
    const float* __restrict__ b_ih, const float* __restrict__ b_hh,
    float* __restrict__ c_st, float* __restrict__ h_out, float* __restrict__ h_save)
{
    extern __shared__ float sm[];
    __shared__ float bias_s[CTA_N];
    lstm_body<K_IN>(blockIdx.x, sm, bias_s, in, h_in, W_ih, W_hh, b_ih, b_hh,
                    c_st, h_out, h_save);
}

// fused: CTAs 0..127 run layer1(t), CTAs 128..255 run layer0(t+1) (independent)
__global__ __launch_bounds__(256, 2) void lstm_step_fused(
    const float* __restrict__ in1, const float* __restrict__ h1_in,
    const float* __restrict__ Wih1, const float* __restrict__ Whh1,
    const float* __restrict__ bih1, const float* __restrict__ bhh1,
    float* __restrict__ c1, float* __restrict__ h1_out, float* __restrict__ h1_save,
    const float* __restrict__ in0, const float* __restrict__ h0_in,
    const float* __restrict__ Wih0, const float* __restrict__ Whh0,
    const float* __restrict__ bih0, const float* __restrict__ bhh0,
    float* __restrict__ c0, float* __restrict__ h0_out)
{
    extern __shared__ float sm[];
    __shared__ float bias_s[CTA_N];
    if (blockIdx.x < 128) {
        lstm_body<HH>(blockIdx.x, sm, bias_s, in1, h1_in, Wih1, Whh1, bih1, bhh1,
                      c1, h1_out, h1_save);
    } else {
        lstm_body<FF>(blockIdx.x - 128, sm, bias_s, in0, h0_in, Wih0, Whh0, bih0, bhh0,
                      c0, h0_out, nullptr);
    }
}

// ---------------- head + output packing ----------------
__global__ void linear_kernel(const float* __restrict__ hin,
                              const float* __restrict__ W_lin,
                              const float* __restrict__ b_lin,
                              float* __restrict__ y) {
    __shared__ float hrow[HH];
    const int b = blockIdx.x;
    for (int i = threadIdx.x; i < HH; i += blockDim.x)
        hrow[i] = hin[(size_t)b * HH + i];
    __syncthreads();
    const int f = threadIdx.x;
    float acc = b_lin[f];
    const float* wv = &W_lin[(size_t)f * HH];
#pragma unroll 4
    for (int k = 0; k < HH; k++) acc += hrow[k] * wv[k];
    y[(size_t)b * FF + f] = acc;
}

__global__ void write_states_kernel(float* __restrict__ out) {
    int i = blockIdx.x * blockDim.x + threadIdx.x;
    if (i >= BB * HH) return;
    const int YO = BB * FF;
    out[YO + i]               = g_h0[0][i];
    out[YO + BB * HH + i]     = g_h1[0][i];
    out[YO + 2 * BB * HH + i] = g_c0[i];
    out[YO + 3 * BB * HH + i] = g_c1[i];
}

extern "C" void kernel_launch(void* const* d_in, const int* in_sizes, int n_in,
                              void* d_out, int out_size) {
    (void)in_sizes; (void)n_in; (void)out_size;
    const float* x     = (const float*)d_in[0];
    const float* W_ih0 = (const float*)d_in[1];
    const float* W_hh0 = (const float*)d_in[2];
    const float* b_ih0 = (const float*)d_in[3];
    const float* b_hh0 = (const float*)d_in[4];
    const float* W_ih1 = (const float*)d_in[5];
    const float* W_hh1 = (const float*)d_in[6];
    const float* b_ih1 = (const float*)d_in[7];
    const float* b_hh1 = (const float*)d_in[8];
    const float* W_lin = (const float*)d_in[9];
    const float* b_lin = (const float*)d_in[10];
    float* out = (float*)d_out;

    cudaFuncSetAttribute(lstm_step_one<FF>, cudaFuncAttributeMaxDynamicSharedMemorySize, SMEM_BYTES);
    cudaFuncSetAttribute(lstm_step_one<HH>, cudaFuncAttributeMaxDynamicSharedMemorySize, SMEM_BYTES);
    cudaFuncSetAttribute(lstm_step_fused,   cudaFuncAttributeMaxDynamicSharedMemorySize, SMEM_BYTES);

    void* p;
    float *ph0, *ph1, *pc0, *pc1, *pfirst, *px, *pWih0, *pWhh0, *pWih1, *pWhh1;
    cudaGetSymbolAddress(&p, g_h0);       ph0    = (float*)p;
    cudaGetSymbolAddress(&p, g_h1);       ph1    = (float*)p;
    cudaGetSymbolAddress(&p, g_c0);       pc0    = (float*)p;
    cudaGetSymbolAddress(&p, g_c1);       pc1    = (float*)p;
    cudaGetSymbolAddress(&p, g_h1_first); pfirst = (float*)p;
    cudaGetSymbolAddress(&p, g_x);        px     = (float*)p;
    cudaGetSymbolAddress(&p, g_Wih0);     pWih0  = (float*)p;
    cudaGetSymbolAddress(&p, g_Whh0);     pWhh0  = (float*)p;
    cudaGetSymbolAddress(&p, g_Wih1);     pWih1  = (float*)p;
    cudaGetSymbolAddress(&p, g_Whh1);     pWhh1  = (float*)p;

    zero_state_kernel<<<(BB * HH + 255) / 256, 256>>>();

    auto prep = [&](const float* src, float* dst, int n) {
        prep_tf32_kernel<<<(n + 255) / 256, 256>>>(src, dst, n);
    };
    prep(x,     px,    TT * BB * FF);
    prep(W_ih0, pWih0, 4 * HH * FF);
    prep(W_hh0, pWhh0, 4 * HH * HH);
    prep(W_ih1, pWih1, 4 * HH * HH);
    prep(W_hh1, pWhh1, 4 * HH * HH);

    // h0 buffers: h0(t) lives in ph0 + (t&1)*BH with h0(0)=zeros in slot 0;
    // layer0 step t consumes x_t and h0 state (t), producing state (t+1) in slot (t+1)&1.
    const size_t BH = (size_t)BB * HH;

    // t=0 of layer 0
    lstm_step_one<FF><<<128, 256, SMEM_BYTES>>>(
        px, ph0 + 0, pWih0, pWhh0, b_ih0, b_hh0, pc0, ph0 + BH, nullptr);

    // software-pipelined: layer1(t) with layer0(t+1)
    for (int t = 0; t < TT - 1; t++) {
        float* h0_cur  = ph0 + ((t + 1) & 1) * BH;  // output of layer0 step t
        float* h0_next = ph0 + ((t + 2) & 1) * BH;
        float* h1_in   = ph1 + (t & 1) * BH;
        float* h1_out  = ph1 + ((t + 1) & 1) * BH;

        lstm_step_fused<<<256, 256, SMEM_BYTES>>>(
            h0_cur, h1_in, pWih1, pWhh1, b_ih1, b_hh1,
            pc1, h1_out, (t == 0) ? pfirst : nullptr,
            px + (size_t)(t + 1) * BB * FF, h0_cur, pWih0, pWhh0, b_ih0, b_hh0,
            pc0, h0_next);
    }

    // final layer1 step t = 255
    lstm_step_one<HH><<<128, 256, SMEM_BYTES>>>(
        ph0 + ((TT) & 1) * BH, ph1 + ((TT - 1) & 1) * BH,
        pWih1, pWhh1, b_ih1, b_hh1, pc1, ph1 + ((TT) & 1) * BH, nullptr);

    linear_kernel<<<BB, FF>>>(pfirst, W_lin, b_lin, out);
    write_states_kernel<<<(BB * HH + 255) / 256, 256>>>(out);
}

// round 5
// speedup vs baseline: 7.0177x; 1.9126x over previous
#include <cuda_runtime.h>
#include <cuda_fp16.h>
#include <math.h>
#include <stdint.h>

// ---------------- problem constants ----------------
#define TT 256
#define BB 256
#define FF 128
#define HH 1024

// ---------------- tiling ----------------
#define KCH     64                         // K halves per chunk
#define CTA_M   64
#define CTA_N   128
#define STAGES  4
#define ROWB    144                        // 72 halves per row (ldmatrix conflict-free)
#define A_BYTES (CTA_M * ROWB)             // 9216
#define W_BYTES (CTA_N * ROWB)             // 18432
#define STAGE_BYTES (A_BYTES + W_BYTES)    // 27648
#define SMEM_BYTES  (STAGES * STAGE_BYTES) // 110592
#define ACC_STRIDE 132

// ---------------- persistent device state ----------------
__device__ float  g_h0f[2][BB * HH];       // fp32 h (outputs)
__device__ float  g_h1f[2][BB * HH];
__device__ __half g_h0h[2][BB * HH];       // fp16 h (GEMM operand)
__device__ __half g_h1h[2][BB * HH];
__device__ float  g_c0[BB * HH];
__device__ float  g_c1[BB * HH];
__device__ float  g_h1_first[BB * HH];
// fp16 operand copies
__device__ __half g_xh[TT * BB * FF];
__device__ __half g_Wih0h[4 * HH * FF];
__device__ __half g_Whh0h[4 * HH * HH];
__device__ __half g_Wih1h[4 * HH * HH];
__device__ __half g_Whh1h[4 * HH * HH];

// ---------------- helpers ----------------
__device__ __forceinline__ uint32_t s2u(const void* p) {
    uint32_t a;
    asm("{ .reg .u64 t; cvta.to.shared.u64 t, %1; cvt.u32.u64 %0, t; }"
        : "=r"(a) : "l"(p));
    return a;
}

__device__ __forceinline__ void cp16(uint32_t s, const void* g) {
    asm volatile("cp.async.cg.shared.global [%0], [%1], 16;" :: "r"(s), "l"(g));
}
#define CP_COMMIT() asm volatile("cp.async.commit_group;" ::: "memory")
#define CP_WAIT(N)  asm volatile("cp.async.wait_group %0;" :: "n"(N) : "memory")

__device__ __forceinline__ void ldsm4(uint32_t* r, uint32_t addr) {
    asm volatile("ldmatrix.sync.aligned.m8n8.x4.shared.b16 {%0,%1,%2,%3}, [%4];"
        : "=r"(r[0]), "=r"(r[1]), "=r"(r[2]), "=r"(r[3]) : "r"(addr));
}

__device__ __forceinline__ void mma16(float* c, const uint32_t* a, uint32_t b0, uint32_t b1) {
    asm volatile(
        "mma.sync.aligned.m16n8k16.row.col.f32.f16.f16.f32 "
        "{%0,%1,%2,%3}, {%4,%5,%6,%7}, {%8,%9}, {%0,%1,%2,%3};"
        : "+f"(c[0]), "+f"(c[1]), "+f"(c[2]), "+f"(c[3])
        : "r"(a[0]), "r"(a[1]), "r"(a[2]), "r"(a[3]), "r"(b0), "r"(b1));
}

__device__ __forceinline__ float sigmoidf_(float x) { return 1.0f / (1.0f + expf(-x)); }

// ---------------- setup kernels ----------------
__global__ void zero_state_kernel() {
    int i = blockIdx.x * blockDim.x + threadIdx.x;
    if (i < BB * HH) {
        g_h0f[0][i] = 0.0f;
        g_h1f[0][i] = 0.0f;
        g_h0h[0][i] = __float2half(0.0f);
        g_h1h[0][i] = __float2half(0.0f);
        g_c0[i] = 0.0f;
        g_c1[i] = 0.0f;
    }
}

__global__ void prep_f16_kernel(const float* __restrict__ in, __half* __restrict__ out, int n) {
    int i = blockIdx.x * blockDim.x + threadIdx.x;
    if (i < n) out[i] = __float2half_rn(in[i]);
}

// ---------------- chunk loader (256 threads) ----------------
__device__ __forceinline__ void load_chunk256(
    uint32_t dstA, uint32_t dstW, int tid,
    const __half* __restrict__ aSrc, int ald,
    const __half* __restrict__ wSrc, int wld, int j0)
{
#pragma unroll
    for (int i = 0; i < 2; i++) {            // A: 64 rows x 8 segs = 512
        int q = tid + i * 256;
        int row = q >> 3, seg = q & 7;
        cp16(dstA + row * ROWB + seg * 16, aSrc + (size_t)row * ald + seg * 8);
    }
#pragma unroll
    for (int i = 0; i < 4; i++) {            // W: 128 rows x 8 segs = 1024
        int q = tid + i * 256;
        int row = q >> 3, seg = q & 7;
        int g = row >> 5, u = row & 31;
        cp16(dstW + row * ROWB + seg * 16,
             wSrc + (size_t)(g * HH + j0 + u) * wld + seg * 8);
    }
    CP_COMMIT();
}

// ---------------- fused LSTM step body (mma.sync fp16, ldmatrix) ----------------
// bid 0..127 = m(0..3) + 4*nt(0..31). CTA: M=64 batch x N=128 (= 4 gates x 32 units).
// 8 warps as 2(m) x 4(n); warp tile 32x32; K chunk = 64 halves.
template <int K_IN>
__device__ __forceinline__ void lstm_body(
    int bid, float* sm, float* bias_s,
    const __half* __restrict__ in,    // (B, K_IN) fp16
    const __half* __restrict__ h_in,  // (B, H)    fp16
    const __half* __restrict__ W_ih,  // (4H, K_IN) fp16
    const __half* __restrict__ W_hh,  // (4H, H)    fp16
    const float* __restrict__ b_ih,
    const float* __restrict__ b_hh,
    float* __restrict__ c_st,         // (B, H) fp32, in-place
    float* __restrict__ h_out_f,      // (B, H) fp32
    __half* __restrict__ h_out_h,     // (B, H) fp16
    float* __restrict__ h_save)
{
    constexpr int NC    = (K_IN + HH) / KCH;
    constexpr int SPLIT = K_IN / KCH;

    const int tid  = threadIdx.x;
    const int w    = tid >> 5;
    const int lane = tid & 31;
    const int wm   = w & 1;          // M half
    const int wn   = w >> 1;         // gate / N block
    const int r4   = lane >> 2, cl = lane & 3;
    const int m    = bid & 3;
    const int nt   = bid >> 2;
    const int b0   = m * CTA_M;
    const int j0   = nt * 32;

    const uint32_t smb = s2u(sm);

    if (tid < CTA_N) {
        int g = tid >> 5, u = tid & 31;
        bias_s[tid] = b_ih[g * HH + j0 + u] + b_hh[g * HH + j0 + u];
    }

    // ldmatrix per-lane byte offsets (within a stage buffer)
    const int arow = (lane & 7) + ((lane >> 3) & 1) * 8;
    const int aseg = (lane >> 4) & 1;
    const uint32_t aoff0 = (uint32_t)((wm * 32 + 0 + arow) * ROWB + aseg * 16);
    const uint32_t aoff1 = (uint32_t)((wm * 32 + 16 + arow) * ROWB + aseg * 16);
    const int brow = (lane & 7) + ((lane >> 4) & 1) * 8;
    const int bseg = (lane >> 3) & 1;
    const uint32_t boffA = (uint32_t)((wn * 32 + 0 + brow) * ROWB + bseg * 16);
    const uint32_t boffB = (uint32_t)((wn * 32 + 16 + brow) * ROWB + bseg * 16);

    float acc[2][4][4];
#pragma unroll
    for (int mi = 0; mi < 2; mi++)
#pragma unroll
        for (int ni = 0; ni < 4; ni++)
#pragma unroll
            for (int q = 0; q < 4; q++) acc[mi][ni][q] = 0.0f;

    auto src_for = [&](int ch, const __half*& as, int& ald, const __half*& ws, int& wld) {
        if (ch < SPLIT) {
            as = in + (size_t)b0 * K_IN + ch * KCH; ald = K_IN;
            ws = W_ih + ch * KCH;                   wld = K_IN;
        } else {
            int ko = (ch - SPLIT) * KCH;
            as = h_in + (size_t)b0 * HH + ko; ald = HH;
            ws = W_hh + ko;                   wld = HH;
        }
    };

#pragma unroll
    for (int s = 0; s < 3; s++) {
        const __half* as; const __half* ws; int ald, wld;
        src_for(s, as, ald, ws, wld);
        load_chunk256(smb + s * STAGE_BYTES, smb + s * STAGE_BYTES + A_BYTES,
                      tid, as, ald, ws, wld, j0);
    }

#pragma unroll 1
    for (int ch = 0; ch < NC; ch++) {
        if (ch >= NC - 1)      { CP_WAIT(0); }
        else if (ch == NC - 2) { CP_WAIT(1); }
        else                   { CP_WAIT(2); }
        __syncthreads();

        if (ch + 3 < NC) {
            const __half* as; const __half* ws; int ald, wld;
            src_for(ch + 3, as, ald, ws, wld);
            int buf = (ch + 3) & 3;
            load_chunk256(smb + buf * STAGE_BYTES, smb + buf * STAGE_BYTES + A_BYTES,
                          tid, as, ald, ws, wld, j0);
        }

        const uint32_t aBase = smb + (ch & 3) * STAGE_BYTES;
        const uint32_t wBase = aBase + A_BYTES;

#pragma unroll
        for (int ks = 0; ks < 4; ks++) {          // 4 k16 steps = 64 halves
            uint32_t a0[4], a1[4], bA[4], bB[4];
            ldsm4(a0, aBase + aoff0 + ks * 32);
            ldsm4(a1, aBase + aoff1 + ks * 32);
            ldsm4(bA, wBase + boffA + ks * 32);
            ldsm4(bB, wBase + boffB + ks * 32);
            mma16(acc[0][0], a0, bA[0], bA[1]);
            mma16(acc[1][0], a1, bA[0], bA[1]);
            mma16(acc[0][1], a0, bA[2], bA[3]);
            mma16(acc[1][1], a1, bA[2], bA[3]);
            mma16(acc[0][2], a0, bB[0], bB[1]);
            mma16(acc[1][2], a1, bB[0], bB[1]);
            mma16(acc[0][3], a0, bB[2], bB[3]);
            mma16(acc[1][3], a1, bB[2], bB[3]);
        }
    }

    // stage accums through SMEM so each thread gathers all 4 gates of a (b,u)
    __syncthreads();
    float* Acc = sm;
#pragma unroll
    for (int mi = 0; mi < 2; mi++)
#pragma unroll
        for (int ni = 0; ni < 4; ni++) {
            int R   = wm * 32 + mi * 16 + r4;
            int col = wn * 32 + ni * 8 + 2 * cl;
            *(float2*)&Acc[R * ACC_STRIDE + col]       = make_float2(acc[mi][ni][0], acc[mi][ni][1]);
            *(float2*)&Acc[(R + 8) * ACC_STRIDE + col] = make_float2(acc[mi][ni][2], acc[mi][ni][3]);
        }
    __syncthreads();

    const int u  = tid & 31;
    const int rb = tid >> 5;
#pragma unroll
    for (int rr = 0; rr < 8; rr++) {
        int r = rb * 8 + rr;
        float iv = Acc[r * ACC_STRIDE + u]      + bias_s[u];
        float fv = Acc[r * ACC_STRIDE + 32 + u] + bias_s[32 + u];
        float gv = Acc[r * ACC_STRIDE + 64 + u] + bias_s[64 + u];
        float ov = Acc[r * ACC_STRIDE + 96 + u] + bias_s[96 + u];
        float ig = sigmoidf_(iv);
        float fg = sigmoidf_(fv);
        float gg = tanhf(gv);
        float og = sigmoidf_(ov);
        size_t idx = (size_t)(b0 + r) * HH + j0 + u;
        float cn = fg * c_st[idx] + ig * gg;
        c_st[idx] = cn;
        float hn = og * tanhf(cn);
        h_out_f[idx] = hn;
        h_out_h[idx] = __float2half_rn(hn);
        if (h_save) h_save[idx] = hn;
    }
}

// standalone single-layer step (grid 128)
template <int K_IN>
__global__ __launch_bounds__(256, 2) void lstm_step_one(
    const __half* __restrict__ in, const __half* __restrict__ h_in,
    const __half* __restrict__ W_ih, const __half* __restrict__ W_hh,
    const float* __restrict__ b_ih, const float* __restrict__ b_hh,
    float* __restrict__ c_st, float* __restrict__ h_out_f,
    __half* __restrict__ h_out_h, float* __restrict__ h_save)
{
    extern __shared__ float sm[];
    __shared__ float bias_s[CTA_N];
    lstm_body<K_IN>(blockIdx.x, sm, bias_s, in, h_in, W_ih, W_hh, b_ih, b_hh,
                    c_st, h_out_f, h_out_h, h_save);
}

// fused: CTAs 0..127 run layer1(t), CTAs 128..255 run layer0(t+1) (independent)
__global__ __launch_bounds__(256, 2) void lstm_step_fused(
    const __half* __restrict__ in1, const __half* __restrict__ h1_in,
    const __half* __restrict__ Wih1, const __half* __restrict__ Whh1,
    const float* __restrict__ bih1, const float* __restrict__ bhh1,
    float* __restrict__ c1, float* __restrict__ h1f, __half* __restrict__ h1h,
    float* __restrict__ h1_save,
    const __half* __restrict__ in0, const __half* __restrict__ h0_in,
    const __half* __restrict__ Wih0, const __half* __restrict__ Whh0,
    const float* __restrict__ bih0, const float* __restrict__ bhh0,
    float* __restrict__ c0, float* __restrict__ h0f, __half* __restrict__ h0h)
{
    extern __shared__ float sm[];
    __shared__ float bias_s[CTA_N];
    if (blockIdx.x < 128) {
        lstm_body<HH>(blockIdx.x, sm, bias_s, in1, h1_in, Wih1, Whh1, bih1, bhh1,
                      c1, h1f, h1h, h1_save);
    } else {
        lstm_body<FF>(blockIdx.x - 128, sm, bias_s, in0, h0_in, Wih0, Whh0, bih0, bhh0,
                      c0, h0f, h0h, nullptr);
    }
}

// ---------------- head + output packing ----------------
__global__ void linear_kernel(const float* __restrict__ hin,
                              const float* __restrict__ W_lin,
                              const float* __restrict__ b_lin,
                              float* __restrict__ y) {
    __shared__ float hrow[HH];
    const int b = blockIdx.x;
    for (int i = threadIdx.x; i < HH; i += blockDim.x)
        hrow[i] = hin[(size_t)b * HH + i];
    __syncthreads();
    const int f = threadIdx.x;
    float acc = b_lin[f];
    const float* wv = &W_lin[(size_t)f * HH];
#pragma unroll 4
    for (int k = 0; k < HH; k++) acc += hrow[k] * wv[k];
    y[(size_t)b * FF + f] = acc;
}

__global__ void write_states_kernel(float* __restrict__ out) {
    int i = blockIdx.x * blockDim.x + threadIdx.x;
    if (i >= BB * HH) return;
    const int YO = BB * FF;
    out[YO + i]               = g_h0f[0][i];
    out[YO + BB * HH + i]     = g_h1f[0][i];
    out[YO + 2 * BB * HH + i] = g_c0[i];
    out[YO + 3 * BB * HH + i] = g_c1[i];
}

extern "C" void kernel_launch(void* const* d_in, const int* in_sizes, int n_in,
                              void* d_out, int out_size) {
    (void)in_sizes; (void)n_in; (void)out_size;
    const float* x     = (const float*)d_in[0];
    const float* W_ih0 = (const float*)d_in[1];
    const float* W_hh0 = (const float*)d_in[2];
    const float* b_ih0 = (const float*)d_in[3];
    const float* b_hh0 = (const float*)d_in[4];
    const float* W_ih1 = (const float*)d_in[5];
    const float* W_hh1 = (const float*)d_in[6];
    const float* b_ih1 = (const float*)d_in[7];
    const float* b_hh1 = (const float*)d_in[8];
    const float* W_lin = (const float*)d_in[9];
    const float* b_lin = (const float*)d_in[10];
    float* out = (float*)d_out;

    cudaFuncSetAttribute(lstm_step_one<FF>, cudaFuncAttributeMaxDynamicSharedMemorySize, SMEM_BYTES);
    cudaFuncSetAttribute(lstm_step_one<HH>, cudaFuncAttributeMaxDynamicSharedMemorySize, SMEM_BYTES);
    cudaFuncSetAttribute(lstm_step_fused,   cudaFuncAttributeMaxDynamicSharedMemorySize, SMEM_BYTES);

    void* p;
    float *ph0f, *ph1f, *pc0, *pc1, *pfirst;
    __half *ph0h, *ph1h, *pxh, *pWih0, *pWhh0, *pWih1, *pWhh1;
    cudaGetSymbolAddress(&p, g_h0f);      ph0f   = (float*)p;
    cudaGetSymbolAddress(&p, g_h1f);      ph1f   = (float*)p;
    cudaGetSymbolAddress(&p, g_h0h);      ph0h   = (__half*)p;
    cudaGetSymbolAddress(&p, g_h1h);      ph1h   = (__half*)p;
    cudaGetSymbolAddress(&p, g_c0);       pc0    = (float*)p;
    cudaGetSymbolAddress(&p, g_c1);       pc1    = (float*)p;
    cudaGetSymbolAddress(&p, g_h1_first); pfirst = (float*)p;
    cudaGetSymbolAddress(&p, g_xh);       pxh    = (__half*)p;
    cudaGetSymbolAddress(&p, g_Wih0h);    pWih0  = (__half*)p;
    cudaGetSymbolAddress(&p, g_Whh0h);    pWhh0  = (__half*)p;
    cudaGetSymbolAddress(&p, g_Wih1h);    pWih1  = (__half*)p;
    cudaGetSymbolAddress(&p, g_Whh1h);    pWhh1  = (__half*)p;

    zero_state_kernel<<<(BB * HH + 255) / 256, 256>>>();

    auto prep = [&](const float* src, __half* dst, int n) {
        prep_f16_kernel<<<(n + 255) / 256, 256>>>(src, dst, n);
    };
    prep(x,     pxh,   TT * BB * FF);
    prep(W_ih0, pWih0, 4 * HH * FF);
    prep(W_hh0, pWhh0, 4 * HH * HH);
    prep(W_ih1, pWih1, 4 * HH * HH);
    prep(W_hh1, pWhh1, 4 * HH * HH);

    const size_t BH = (size_t)BB * HH;

    // t=0 of layer 0
    lstm_step_one<FF><<<128, 256, SMEM_BYTES>>>(
        pxh, ph0h + 0, pWih0, pWhh0, b_ih0, b_hh0,
        pc0, ph0f + BH, ph0h + BH, nullptr);

    // software-pipelined: layer1(t) with layer0(t+1)
    for (int t = 0; t < TT - 1; t++) {
        __half* h0h_cur  = ph0h + ((t + 1) & 1) * BH;  // output of layer0 step t
        float*  h0f_next = ph0f + ((t + 2) & 1) * BH;
        __half* h0h_next = ph0h + ((t + 2) & 1) * BH;
        __half* h1h_in   = ph1h + (t & 1) * BH;
        float*  h1f_out  = ph1f + ((t + 1) & 1) * BH;
        __half* h1h_out  = ph1h + ((t + 1) & 1) * BH;

        lstm_step_fused<<<256, 256, SMEM_BYTES>>>(
            h0h_cur, h1h_in, pWih1, pWhh1, b_ih1, b_hh1,
            pc1, h1f_out, h1h_out, (t == 0) ? pfirst : nullptr,
            pxh + (size_t)(t + 1) * BB * FF, h0h_cur, pWih0, pWhh0, b_ih0, b_hh0,
            pc0, h0f_next, h0h_next);
    }

    // final layer1 step t = 255
    lstm_step_one<HH><<<128, 256, SMEM_BYTES>>>(
        ph0h + (TT & 1) * BH, ph1h + ((TT - 1) & 1) * BH,
        pWih1, pWhh1, b_ih1, b_hh1,
        pc1, ph1f + (TT & 1) * BH, ph1h + (TT & 1) * BH, nullptr);

    linear_kernel<<<BB, FF>>>(pfirst, W_lin, b_lin, out);
    write_states_kernel<<<(BB * HH + 255) / 256, 256>>>(out);
}

// round 6
// speedup vs baseline: 7.4660x; 1.0639x over previous
#include <cuda_runtime.h>
#include <cuda_fp16.h>
#include <math.h>
#include <stdint.h>

// ---------------- problem constants ----------------
#define TT 256
#define BB 256
#define FF 128
#define HH 1024

// ---------------- tiling ----------------
#define KCH     64                         // K halves per chunk
#define CTA_M   64
#define CTA_N   128
#define ROWB    144                        // 72 halves per row
#define A_BYTES (CTA_M * ROWB)             // 9216
#define W_BYTES (CTA_N * ROWB)             // 18432
#define STAGE_BYTES (A_BYTES + W_BYTES)    // 27648
#define SMEM_BYTES  (4 * STAGE_BYTES)      // 110592

// ---------------- persistent device state ----------------
__device__ __half g_h0h[2][BB * HH];
__device__ __half g_h1h[2][BB * HH];
__device__ __half g_xh[TT * BB * FF];
__device__ __half g_Wih0h[4 * HH * FF];
__device__ __half g_Whh0h[4 * HH * HH];
__device__ __half g_Wih1h[4 * HH * HH];
__device__ __half g_Whh1h[4 * HH * HH];
__device__ float  g_h0fin[BB * HH];
__device__ float  g_h1fin[BB * HH];
__device__ float  g_c0fin[BB * HH];
__device__ float  g_c1fin[BB * HH];
__device__ float  g_h1first[BB * HH];
__device__ uint32_t g_flag0[TT * 4];   // layer0 step done (per m group)
__device__ uint32_t g_flag1[TT * 4];   // layer1 step done
__device__ uint32_t g_cons[TT * 4];    // layer1 consumed h0(s+1)

// ---------------- helpers ----------------
__device__ __forceinline__ uint32_t s2u(const void* p) {
    uint32_t a;
    asm("{ .reg .u64 t; cvta.to.shared.u64 t, %1; cvt.u32.u64 %0, t; }"
        : "=r"(a) : "l"(p));
    return a;
}

__device__ __forceinline__ void cp16(uint32_t s, const void* g) {
    asm volatile("cp.async.cg.shared.global [%0], [%1], 16;" :: "r"(s), "l"(g));
}
#define CP_COMMIT() asm volatile("cp.async.commit_group;" ::: "memory")
#define CP_WAIT(N)  asm volatile("cp.async.wait_group %0;" :: "n"(N) : "memory")

__device__ __forceinline__ void ldsm4(uint32_t* r, uint32_t addr) {
    asm volatile("ldmatrix.sync.aligned.m8n8.x4.shared.b16 {%0,%1,%2,%3}, [%4];"
        : "=r"(r[0]), "=r"(r[1]), "=r"(r[2]), "=r"(r[3]) : "r"(addr));
}

__device__ __forceinline__ void mma16(float* c, const uint32_t* a, uint32_t b0, uint32_t b1) {
    asm volatile(
        "mma.sync.aligned.m16n8k16.row.col.f32.f16.f16.f32 "
        "{%0,%1,%2,%3}, {%4,%5,%6,%7}, {%8,%9}, {%0,%1,%2,%3};"
        : "+f"(c[0]), "+f"(c[1]), "+f"(c[2]), "+f"(c[3])
        : "r"(a[0]), "r"(a[1]), "r"(a[2]), "r"(a[3]), "r"(b0), "r"(b1));
}

__device__ __forceinline__ void spin_ge(const uint32_t* p, uint32_t tgt) {
    uint32_t v;
    while (true) {
        asm volatile("ld.acquire.gpu.global.u32 %0, [%1];" : "=r"(v) : "l"(p) : "memory");
        if (v >= tgt) break;
        __nanosleep(32);
    }
}

__device__ __forceinline__ void rel_add(uint32_t* p) {
    asm volatile("red.release.gpu.global.add.u32 [%0], 1;" :: "l"(p) : "memory");
}

__device__ __forceinline__ float sigmoidf_(float x) { return 1.0f / (1.0f + expf(-x)); }

// ---------------- one-shot prep: fp16 conversions + state/flag zeroing ----------------
#define N_X   (TT * BB * FF)
#define N_WI0 (4 * HH * FF)
#define N_WHH (4 * HH * HH)
#define N_Z   (BB * HH)
#define PREP_TOTAL (N_X + N_WI0 + 3 * N_WHH + 2 * N_Z + 3 * TT * 4)

__global__ void prep_all(const float* __restrict__ x,
                         const float* __restrict__ wi0, const float* __restrict__ wh0,
                         const float* __restrict__ wi1, const float* __restrict__ wh1) {
    long long i = (long long)blockIdx.x * blockDim.x + threadIdx.x;
    if (i >= PREP_TOTAL) return;
    if (i < N_X) { g_xh[i] = __float2half_rn(x[i]); return; }
    i -= N_X;
    if (i < N_WI0) { g_Wih0h[i] = __float2half_rn(wi0[i]); return; }
    i -= N_WI0;
    if (i < N_WHH) { g_Whh0h[i] = __float2half_rn(wh0[i]); return; }
    i -= N_WHH;
    if (i < N_WHH) { g_Wih1h[i] = __float2half_rn(wi1[i]); return; }
    i -= N_WHH;
    if (i < N_WHH) { g_Whh1h[i] = __float2half_rn(wh1[i]); return; }
    i -= N_WHH;
    if (i < N_Z) { g_h0h[0][i] = __float2half(0.0f); return; }
    i -= N_Z;
    if (i < N_Z) { g_h1h[0][i] = __float2half(0.0f); return; }
    i -= N_Z;
    if (i < TT * 4)     { g_flag0[i] = 0; return; }
    i -= TT * 4;
    if (i < TT * 4)     { g_flag1[i] = 0; return; }
    i -= TT * 4;
    g_cons[i] = 0;
}

// ---------------- chunk loader (256 threads) ----------------
__device__ __forceinline__ void load_chunk256(
    uint32_t dstA, uint32_t dstW, int tid,
    const __half* __restrict__ aSrc, int ald,
    const __half* __restrict__ wSrc, int wld, int j0)
{
#pragma unroll
    for (int i = 0; i < 2; i++) {            // A: 64 rows x 8 segs
        int q = tid + i * 256;
        int row = q >> 3, seg = q & 7;
        cp16(dstA + row * ROWB + seg * 16, aSrc + (size_t)row * ald + seg * 8);
    }
#pragma unroll
    for (int i = 0; i < 4; i++) {            // W: 128 rows x 8 segs
        int q = tid + i * 256;
        int row = q >> 3, seg = q & 7;
        int g = row >> 5, u = row & 31;
        cp16(dstW + row * ROWB + seg * 16,
             wSrc + (size_t)(g * HH + j0 + u) * wld + seg * 8);
    }
    CP_COMMIT();
}

// ---------------- persistent per-CTA loop ----------------
// bid 0..127: m = bid&3 (batch 64-tile), nt = bid>>2 (32-unit tile).
// Warp tiling: 8 warps = 2(m) x 4(n); warp wn covers units [8wn,8wn+8) for ALL
// 4 gates (N fragments = gates) so the LSTM cell update is thread-local and c
// stays in registers across all 256 steps.
template <int K_IN, int LAYER>
__device__ __forceinline__ void lstm_run(int bid, char* smraw, float* bias_s,
                                         const float* __restrict__ b_ih,
                                         const float* __restrict__ b_hh) {
    constexpr int NC    = (K_IN + HH) / KCH;     // 32 (L1) / 18 (L0)
    constexpr int SPLIT = K_IN / KCH;            // 16 (L1) / 2  (L0)

    const int tid  = threadIdx.x;
    const int w    = tid >> 5;
    const int lane = tid & 31;
    const int wm   = w & 1;
    const int wn   = w >> 1;
    const int r4   = lane >> 2, cl = lane & 3;
    const int m    = bid & 3;
    const int nt   = bid >> 2;
    const int b0   = m * CTA_M;
    const int j0   = nt * 32;

    const uint32_t smb = s2u(smraw);
    const __half* Wih = LAYER ? g_Wih1h : g_Wih0h;
    const __half* Whh = LAYER ? g_Whh1h : g_Whh0h;

    if (tid < CTA_N) {
        int g = tid >> 5, u = tid & 31;
        bias_s[tid] = b_ih[g * HH + j0 + u] + b_hh[g * HH + j0 + u];
    }
    __syncthreads();

    // fragment smem offsets (within a stage buffer)
    const int arow = (lane & 7) + ((lane >> 3) & 1) * 8;
    const int aseg = (lane >> 4) & 1;
    const uint32_t aoff0 = (uint32_t)((wm * 32 + arow) * ROWB + aseg * 16);
    const uint32_t aoff1 = (uint32_t)((wm * 32 + 16 + arow) * ROWB + aseg * 16);
    // B: ldsm matrices = (gate 0|1 selected by lane>>4, kseg by lane bit3)
    const uint32_t boffA = (uint32_t)((((lane >> 4) & 1) * 32 + wn * 8 + (lane & 7)) * ROWB
                                      + ((lane >> 3) & 1) * 16);
    const uint32_t boffB = boffA + 64u * ROWB;

    float c_reg[2][2][2];
#pragma unroll
    for (int a = 0; a < 2; a++)
#pragma unroll
        for (int b = 0; b < 2; b++)
#pragma unroll
            for (int d = 0; d < 2; d++) c_reg[a][b][d] = 0.0f;

#pragma unroll 1
    for (int s = 0; s < TT; s++) {
        const __half* inP = LAYER ? g_h0h[(s + 1) & 1]
                                  : g_xh + (size_t)s * BB * FF;
        const __half* hP  = LAYER ? g_h1h[s & 1] : g_h0h[s & 1];

        // layer1: h0(s+1) must be complete before any prologue load
        if (LAYER == 1) {
            if (tid == 0) spin_ge(&g_flag0[s * 4 + m], 32);
            __syncthreads();
        }

        auto src_for = [&](int ch, const __half*& as, int& ald,
                           const __half*& ws, int& wld) {
            if (ch < SPLIT) {
                as = inP + (size_t)b0 * K_IN + ch * KCH; ald = K_IN;
                ws = Wih + ch * KCH;                     wld = K_IN;
            } else {
                int ko = (ch - SPLIT) * KCH;
                as = hP + (size_t)b0 * HH + ko; ald = HH;
                ws = Whh + ko;                  wld = HH;
            }
        };

        // prologue (3 stages); layer0: gate h0(s) before its first h chunk (chunk 2)
#pragma unroll
        for (int st = 0; st < 3; st++) {
            if (LAYER == 0 && st == SPLIT && s > 0) {
                if (tid == 0) spin_ge(&g_flag0[(s - 1) * 4 + m], 32);
                __syncthreads();
            }
            const __half* as; const __half* ws; int ald, wld;
            src_for(st, as, ald, ws, wld);
            load_chunk256(smb + st * STAGE_BYTES, smb + st * STAGE_BYTES + A_BYTES,
                          tid, as, ald, ws, wld, j0);
        }

        float acc[2][4][4];
#pragma unroll
        for (int mi = 0; mi < 2; mi++)
#pragma unroll
            for (int g = 0; g < 4; g++)
#pragma unroll
                for (int q = 0; q < 4; q++) acc[mi][g][q] = 0.0f;

#pragma unroll 1
        for (int ch = 0; ch < NC; ch++) {
            if (ch >= NC - 1)      { CP_WAIT(0); }
            else if (ch == NC - 2) { CP_WAIT(1); }
            else                   { CP_WAIT(2); }
            __syncthreads();

            // layer1: gate h1(s) just before the first h1 chunk prefetch
            if (LAYER == 1 && s > 0 && ch == SPLIT - 3) {
                if (tid == 0) spin_ge(&g_flag1[(s - 1) * 4 + m], 32);
                __syncthreads();
            }

            if (ch + 3 < NC) {
                const __half* as; const __half* ws; int ald, wld;
                src_for(ch + 3, as, ald, ws, wld);
                int buf = (ch + 3) & 3;
                load_chunk256(smb + buf * STAGE_BYTES, smb + buf * STAGE_BYTES + A_BYTES,
                              tid, as, ald, ws, wld, j0);
            }

            const uint32_t aBase = smb + (ch & 3) * STAGE_BYTES;
            const uint32_t wBase = aBase + A_BYTES;

#pragma unroll
            for (int ks = 0; ks < 4; ks++) {
                uint32_t a0[4], a1[4], bA[4], bB[4];
                ldsm4(a0, aBase + aoff0 + ks * 32);
                ldsm4(a1, aBase + aoff1 + ks * 32);
                ldsm4(bA, wBase + boffA + ks * 32);
                ldsm4(bB, wBase + boffB + ks * 32);
                mma16(acc[0][0], a0, bA[0], bA[1]);
                mma16(acc[1][0], a1, bA[0], bA[1]);
                mma16(acc[0][1], a0, bA[2], bA[3]);
                mma16(acc[1][1], a1, bA[2], bA[3]);
                mma16(acc[0][2], a0, bB[0], bB[1]);
                mma16(acc[1][2], a1, bB[0], bB[1]);
                mma16(acc[0][3], a0, bB[2], bB[3]);
                mma16(acc[1][3], a1, bB[2], bB[3]);
            }
        }

        __syncthreads();
        // layer1: signal h0(s+1) fully consumed (all global reads landed)
        if (LAYER == 1 && tid == 0) rel_add(&g_cons[s * 4 + m]);
        // layer0: before overwriting h0 slot (s+1)&1 (= h0(s-1)), wait until
        // layer1 step s-2 consumed it
        if (LAYER == 0 && s >= 2) {
            if (tid == 0) spin_ge(&g_cons[(s - 2) * 4 + m], 32);
            __syncthreads();
        }

        // epilogue: thread-local cell update, c in registers
        __half* hOut = (LAYER ? g_h1h : g_h0h)[(s + 1) & 1];
#pragma unroll
        for (int mi = 0; mi < 2; mi++)
#pragma unroll
            for (int rh = 0; rh < 2; rh++) {
                const int row = b0 + wm * 32 + mi * 16 + r4 + rh * 8;
                const int col = j0 + wn * 8 + 2 * cl;
                float hv[2];
#pragma unroll
                for (int du = 0; du < 2; du++) {
                    const int q = rh * 2 + du;
                    const int ul = wn * 8 + 2 * cl + du;
                    float iv = acc[mi][0][q] + bias_s[ul];
                    float fv = acc[mi][1][q] + bias_s[32 + ul];
                    float gv = acc[mi][2][q] + bias_s[64 + ul];
                    float ov = acc[mi][3][q] + bias_s[96 + ul];
                    float cn = sigmoidf_(fv) * c_reg[mi][rh][du]
                             + sigmoidf_(iv) * tanhf(gv);
                    c_reg[mi][rh][du] = cn;
                    hv[du] = sigmoidf_(ov) * tanhf(cn);
                }
                *(__half2*)&hOut[(size_t)row * HH + col] =
                    __floats2half2_rn(hv[0], hv[1]);
                if (LAYER == 1 && s == 0)
                    *(float2*)&g_h1first[(size_t)row * HH + col] = make_float2(hv[0], hv[1]);
                if (s == TT - 1) {
                    float* hf = LAYER ? g_h1fin : g_h0fin;
                    float* cf = LAYER ? g_c1fin : g_c0fin;
                    *(float2*)&hf[(size_t)row * HH + col] = make_float2(hv[0], hv[1]);
                    *(float2*)&cf[(size_t)row * HH + col] =
                        make_float2(c_reg[mi][rh][0], c_reg[mi][rh][1]);
                }
            }
        __syncthreads();
        if (tid == 0) rel_add(LAYER ? &g_flag1[s * 4 + m] : &g_flag0[s * 4 + m]);
    }
}

__global__ __launch_bounds__(256, 2) void lstm_persistent(
    const float* __restrict__ bih0, const float* __restrict__ bhh0,
    const float* __restrict__ bih1, const float* __restrict__ bhh1) {
    extern __shared__ char smraw[];
    __shared__ float bias_s[CTA_N];
    if (blockIdx.x < 128)
        lstm_run<HH, 1>(blockIdx.x, smraw, bias_s, bih1, bhh1);
    else
        lstm_run<FF, 0>(blockIdx.x - 128, smraw, bias_s, bih0, bhh0);
}

// ---------------- head + output packing ----------------
__global__ void linear_kernel(const float* __restrict__ W_lin,
                              const float* __restrict__ b_lin,
                              float* __restrict__ y) {
    __shared__ float hrow[HH];
    const int b = blockIdx.x;
    for (int i = threadIdx.x; i < HH; i += blockDim.x)
        hrow[i] = g_h1first[(size_t)b * HH + i];
    __syncthreads();
    const int f = threadIdx.x;
    float acc = b_lin[f];
    const float* wv = &W_lin[(size_t)f * HH];
#pragma unroll 4
    for (int k = 0; k < HH; k++) acc += hrow[k] * wv[k];
    y[(size_t)b * FF + f] = acc;
}

__global__ void write_states_kernel(float* __restrict__ out) {
    int i = blockIdx.x * blockDim.x + threadIdx.x;
    if (i >= BB * HH) return;
    const int YO = BB * FF;
    out[YO + i]               = g_h0fin[i];
    out[YO + BB * HH + i]     = g_h1fin[i];
    out[YO + 2 * BB * HH + i] = g_c0fin[i];
    out[YO + 3 * BB * HH + i] = g_c1fin[i];
}

extern "C" void kernel_launch(void* const* d_in, const int* in_sizes, int n_in,
                              void* d_out, int out_size) {
    (void)in_sizes; (void)n_in; (void)out_size;
    const float* x     = (const float*)d_in[0];
    const float* W_ih0 = (const float*)d_in[1];
    const float* W_hh0 = (const float*)d_in[2];
    const float* b_ih0 = (const float*)d_in[3];
    const float* b_hh0 = (const float*)d_in[4];
    const float* W_ih1 = (const float*)d_in[5];
    const float* W_hh1 = (const float*)d_in[6];
    const float* b_ih1 = (const float*)d_in[7];
    const float* b_hh1 = (const float*)d_in[8];
    const float* W_lin = (const float*)d_in[9];
    const float* b_lin = (const float*)d_in[10];
    float* out = (float*)d_out;

    cudaFuncSetAttribute(lstm_persistent,
                         cudaFuncAttributeMaxDynamicSharedMemorySize, SMEM_BYTES);

    prep_all<<<(PREP_TOTAL + 255) / 256, 256>>>(x, W_ih0, W_hh0, W_ih1, W_hh1);
    lstm_persistent<<<256, 256, SMEM_BYTES>>>(b_ih0, b_hh0, b_ih1, b_hh1);
    linear_kernel<<<BB, FF>>>(W_lin, b_lin, out);
    write_states_kernel<<<(BB * HH + 255) / 256, 256>>>(out);
}

// round 7
// speedup vs baseline: 7.4702x; 1.0006x over previous
#include <cuda_runtime.h>
#include <cuda_fp16.h>
#include <math.h>
#include <stdint.h>

// ---------------- problem constants ----------------
#define TT 256
#define BB 256
#define FF 128
#define HH 1024

// ---------------- tiling ----------------
#define KCH     64                         // K halves per chunk
#define CTA_M   64
#define CTA_N   128
#define ROWB    144                        // 72 halves per row
#define A_BYTES (CTA_M * ROWB)             // 9216
#define W_BYTES (CTA_N * ROWB)             // 18432
#define STAGE_BYTES (A_BYTES + W_BYTES)    // 27648
#define SMEM_BYTES  (4 * STAGE_BYTES)      // 110592

// ---------------- persistent device state ----------------
__device__ __half g_h0h[2][BB * HH];
__device__ __half g_h1h[2][BB * HH];
__device__ __half g_xh[TT * BB * FF];
__device__ __half g_Wih0h[4 * HH * FF];
__device__ __half g_Whh0h[4 * HH * HH];
__device__ __half g_Wih1h[4 * HH * HH];
__device__ __half g_Whh1h[4 * HH * HH];
__device__ float  g_h0fin[BB * HH];
__device__ float  g_h1fin[BB * HH];
__device__ float  g_c0fin[BB * HH];
__device__ float  g_c1fin[BB * HH];
__device__ float  g_h1first[BB * HH];
__device__ uint32_t g_flag0[TT * 4];   // layer0 step done (per m group)
__device__ uint32_t g_flag1[TT * 4];   // layer1 step done
__device__ uint32_t g_cons[TT * 4];    // layer1 consumed h0(s+1)

// ---------------- helpers ----------------
__device__ __forceinline__ uint32_t s2u(const void* p) {
    uint32_t a;
    asm("{ .reg .u64 t; cvta.to.shared.u64 t, %1; cvt.u32.u64 %0, t; }"
        : "=r"(a) : "l"(p));
    return a;
}

__device__ __forceinline__ void cp16(uint32_t s, const void* g) {
    asm volatile("cp.async.cg.shared.global [%0], [%1], 16;" :: "r"(s), "l"(g));
}
#define CP_COMMIT() asm volatile("cp.async.commit_group;" ::: "memory")
#define CP_WAIT(N)  asm volatile("cp.async.wait_group %0;" :: "n"(N) : "memory")

__device__ __forceinline__ void ldsm4(uint32_t* r, uint32_t addr) {
    asm volatile("ldmatrix.sync.aligned.m8n8.x4.shared.b16 {%0,%1,%2,%3}, [%4];"
        : "=r"(r[0]), "=r"(r[1]), "=r"(r[2]), "=r"(r[3]) : "r"(addr));
}

__device__ __forceinline__ void mma16(float* c, const uint32_t* a, uint32_t b0, uint32_t b1) {
    asm volatile(
        "mma.sync.aligned.m16n8k16.row.col.f32.f16.f16.f32 "
        "{%0,%1,%2,%3}, {%4,%5,%6,%7}, {%8,%9}, {%0,%1,%2,%3};"
        : "+f"(c[0]), "+f"(c[1]), "+f"(c[2]), "+f"(c[3])
        : "r"(a[0]), "r"(a[1]), "r"(a[2]), "r"(a[3]), "r"(b0), "r"(b1));
}

__device__ __forceinline__ void spin_ge(const uint32_t* p, uint32_t tgt) {
    uint32_t v;
    while (true) {
        asm volatile("ld.acquire.gpu.global.u32 %0, [%1];" : "=r"(v) : "l"(p) : "memory");
        if (v >= tgt) break;
        __nanosleep(32);
    }
}

__device__ __forceinline__ void rel_add(uint32_t* p) {
    asm volatile("red.release.gpu.global.add.u32 [%0], 1;" :: "l"(p) : "memory");
}

__device__ __forceinline__ float sigmoidf_(float x) { return 1.0f / (1.0f + expf(-x)); }

// ---------------- one-shot prep: fp16 conversions + state/flag zeroing ----------------
#define N_X   (TT * BB * FF)
#define N_WI0 (4 * HH * FF)
#define N_WHH (4 * HH * HH)
#define N_Z   (BB * HH)
#define PREP_TOTAL (N_X + N_WI0 + 3 * N_WHH + 2 * N_Z + 3 * TT * 4)

__global__ void prep_all(const float* __restrict__ x,
                         const float* __restrict__ wi0, const float* __restrict__ wh0,
                         const float* __restrict__ wi1, const float* __restrict__ wh1) {
    long long i = (long long)blockIdx.x * blockDim.x + threadIdx.x;
    if (i >= PREP_TOTAL) return;
    if (i < N_X) { g_xh[i] = __float2half_rn(x[i]); return; }
    i -= N_X;
    if (i < N_WI0) { g_Wih0h[i] = __float2half_rn(wi0[i]); return; }
    i -= N_WI0;
    if (i < N_WHH) { g_Whh0h[i] = __float2half_rn(wh0[i]); return; }
    i -= N_WHH;
    if (i < N_WHH) { g_Wih1h[i] = __float2half_rn(wi1[i]); return; }
    i -= N_WHH;
    if (i < N_WHH) { g_Whh1h[i] = __float2half_rn(wh1[i]); return; }
    i -= N_WHH;
    if (i < N_Z) { g_h0h[0][i] = __float2half(0.0f); return; }
    i -= N_Z;
    if (i < N_Z) { g_h1h[0][i] = __float2half(0.0f); return; }
    i -= N_Z;
    if (i < TT * 4)     { g_flag0[i] = 0; return; }
    i -= TT * 4;
    if (i < TT * 4)     { g_flag1[i] = 0; return; }
    i -= TT * 4;
    g_cons[i] = 0;
}

// ---------------- chunk loader (256 threads) ----------------
__device__ __forceinline__ void load_chunk256(
    uint32_t dstA, uint32_t dstW, int tid,
    const __half* __restrict__ aSrc, int ald,
    const __half* __restrict__ wSrc, int wld, int j0)
{
#pragma unroll
    for (int i = 0; i < 2; i++) {            // A: 64 rows x 8 segs
        int q = tid + i * 256;
        int row = q >> 3, seg = q & 7;
        cp16(dstA + row * ROWB + seg * 16, aSrc + (size_t)row * ald + seg * 8);
    }
#pragma unroll
    for (int i = 0; i < 4; i++) {            // W: 128 rows x 8 segs
        int q = tid + i * 256;
        int row = q >> 3, seg = q & 7;
        int g = row >> 5, u = row & 31;
        cp16(dstW + row * ROWB + seg * 16,
             wSrc + (size_t)(g * HH + j0 + u) * wld + seg * 8);
    }
    CP_COMMIT();
}

// ---------------- persistent per-CTA loop ----------------
// bid 0..127: m = bid&3 (batch 64-tile), nt = bid>>2 (32-unit tile).
// Warp tiling: 8 warps = 2(m) x 4(n); warp wn covers units [8wn,8wn+8) for ALL
// 4 gates (N fragments = gates) so the LSTM cell update is thread-local and c
// stays in registers across all 256 steps.
template <int K_IN, int LAYER>
__device__ __forceinline__ void lstm_run(int bid, char* smraw, float* bias_s,
                                         const float* __restrict__ b_ih,
                                         const float* __restrict__ b_hh) {
    constexpr int NC    = (K_IN + HH) / KCH;     // 32 (L1) / 18 (L0)
    constexpr int SPLIT = K_IN / KCH;            // 16 (L1) / 2  (L0)

    const int tid  = threadIdx.x;
    const int w    = tid >> 5;
    const int lane = tid & 31;
    const int wm   = w & 1;
    const int wn   = w >> 1;
    const int r4   = lane >> 2, cl = lane & 3;
    const int m    = bid & 3;
    const int nt   = bid >> 2;
    const int b0   = m * CTA_M;
    const int j0   = nt * 32;

    const uint32_t smb = s2u(smraw);
    const __half* Wih = LAYER ? g_Wih1h : g_Wih0h;
    const __half* Whh = LAYER ? g_Whh1h : g_Whh0h;

    if (tid < CTA_N) {
        int g = tid >> 5, u = tid & 31;
        bias_s[tid] = b_ih[g * HH + j0 + u] + b_hh[g * HH + j0 + u];
    }
    __syncthreads();

    // fragment smem offsets (within a stage buffer)
    const int arow = (lane & 7) + ((lane >> 3) & 1) * 8;
    const int aseg = (lane >> 4) & 1;
    const uint32_t aoff0 = (uint32_t)((wm * 32 + arow) * ROWB + aseg * 16);
    const uint32_t aoff1 = (uint32_t)((wm * 32 + 16 + arow) * ROWB + aseg * 16);
    // B: ldsm matrices = (gate 0|1 selected by lane>>4, kseg by lane bit3)
    const uint32_t boffA = (uint32_t)((((lane >> 4) & 1) * 32 + wn * 8 + (lane & 7)) * ROWB
                                      + ((lane >> 3) & 1) * 16);
    const uint32_t boffB = boffA + 64u * ROWB;

    float c_reg[2][2][2];
#pragma unroll
    for (int a = 0; a < 2; a++)
#pragma unroll
        for (int b = 0; b < 2; b++)
#pragma unroll
            for (int d = 0; d < 2; d++) c_reg[a][b][d] = 0.0f;

#pragma unroll 1
    for (int s = 0; s < TT; s++) {
        const __half* inP = LAYER ? g_h0h[(s + 1) & 1]
                                  : g_xh + (size_t)s * BB * FF;
        const __half* hP  = LAYER ? g_h1h[s & 1] : g_h0h[s & 1];

        // layer1: h0(s+1) must be complete before any prologue load
        if (LAYER == 1) {
            if (tid == 0) spin_ge(&g_flag0[s * 4 + m], 32);
            __syncthreads();
        }

        auto src_for = [&](int ch, const __half*& as, int& ald,
                           const __half*& ws, int& wld) {
            if (ch < SPLIT) {
                as = inP + (size_t)b0 * K_IN + ch * KCH; ald = K_IN;
                ws = Wih + ch * KCH;                     wld = K_IN;
            } else {
                int ko = (ch - SPLIT) * KCH;
                as = hP + (size_t)b0 * HH + ko; ald = HH;
                ws = Whh + ko;                  wld = HH;
            }
        };

        // prologue (3 stages); layer0: gate h0(s) before its first h chunk (chunk 2)
#pragma unroll
        for (int st = 0; st < 3; st++) {
            if (LAYER == 0 && st == SPLIT && s > 0) {
                if (tid == 0) spin_ge(&g_flag0[(s - 1) * 4 + m], 32);
                __syncthreads();
            }
            const __half* as; const __half* ws; int ald, wld;
            src_for(st, as, ald, ws, wld);
            load_chunk256(smb + st * STAGE_BYTES, smb + st * STAGE_BYTES + A_BYTES,
                          tid, as, ald, ws, wld, j0);
        }

        float acc[2][4][4];
#pragma unroll
        for (int mi = 0; mi < 2; mi++)
#pragma unroll
            for (int g = 0; g < 4; g++)
#pragma unroll
                for (int q = 0; q < 4; q++) acc[mi][g][q] = 0.0f;

#pragma unroll 1
        for (int ch = 0; ch < NC; ch++) {
            if (ch >= NC - 1)      { CP_WAIT(0); }
            else if (ch == NC - 2) { CP_WAIT(1); }
            else                   { CP_WAIT(2); }
            __syncthreads();

            // layer1: gate h1(s) just before the first h1 chunk prefetch
            if (LAYER == 1 && s > 0 && ch == SPLIT - 3) {
                if (tid == 0) spin_ge(&g_flag1[(s - 1) * 4 + m], 32);
                __syncthreads();
            }

            if (ch + 3 < NC) {
                const __half* as; const __half* ws; int ald, wld;
                src_for(ch + 3, as, ald, ws, wld);
                int buf = (ch + 3) & 3;
                load_chunk256(smb + buf * STAGE_BYTES, smb + buf * STAGE_BYTES + A_BYTES,
                              tid, as, ald, ws, wld, j0);
            }

            const uint32_t aBase = smb + (ch & 3) * STAGE_BYTES;
            const uint32_t wBase = aBase + A_BYTES;

#pragma unroll
            for (int ks = 0; ks < 4; ks++) {
                uint32_t a0[4], a1[4], bA[4], bB[4];
                ldsm4(a0, aBase + aoff0 + ks * 32);
                ldsm4(a1, aBase + aoff1 + ks * 32);
                ldsm4(bA, wBase + boffA + ks * 32);
                ldsm4(bB, wBase + boffB + ks * 32);
                mma16(acc[0][0], a0, bA[0], bA[1]);
                mma16(acc[1][0], a1, bA[0], bA[1]);
                mma16(acc[0][1], a0, bA[2], bA[3]);
                mma16(acc[1][1], a1, bA[2], bA[3]);
                mma16(acc[0][2], a0, bB[0], bB[1]);
                mma16(acc[1][2], a1, bB[0], bB[1]);
                mma16(acc[0][3], a0, bB[2], bB[3]);
                mma16(acc[1][3], a1, bB[2], bB[3]);
            }
        }

        __syncthreads();
        // layer1: signal h0(s+1) fully consumed (all global reads landed)
        if (LAYER == 1 && tid == 0) rel_add(&g_cons[s * 4 + m]);
        // layer0: before overwriting h0 slot (s+1)&1 (= h0(s-1)), wait until
        // layer1 step s-2 consumed it
        if (LAYER == 0 && s >= 2) {
            if (tid == 0) spin_ge(&g_cons[(s - 2) * 4 + m], 32);
            __syncthreads();
        }

        // epilogue: thread-local cell update, c in registers
        __half* hOut = (LAYER ? g_h1h : g_h0h)[(s + 1) & 1];
#pragma unroll
        for (int mi = 0; mi < 2; mi++)
#pragma unroll
            for (int rh = 0; rh < 2; rh++) {
                const int row = b0 + wm * 32 + mi * 16 + r4 + rh * 8;
                const int col = j0 + wn * 8 + 2 * cl;
                float hv[2];
#pragma unroll
                for (int du = 0; du < 2; du++) {
                    const int q = rh * 2 + du;
                    const int ul = wn * 8 + 2 * cl + du;
                    float iv = acc[mi][0][q] + bias_s[ul];
                    float fv = acc[mi][1][q] + bias_s[32 + ul];
                    float gv = acc[mi][2][q] + bias_s[64 + ul];
                    float ov = acc[mi][3][q] + bias_s[96 + ul];
                    float cn = sigmoidf_(fv) * c_reg[mi][rh][du]
                             + sigmoidf_(iv) * tanhf(gv);
                    c_reg[mi][rh][du] = cn;
                    hv[du] = sigmoidf_(ov) * tanhf(cn);
                }
                *(__half2*)&hOut[(size_t)row * HH + col] =
                    __floats2half2_rn(hv[0], hv[1]);
                if (LAYER == 1 && s == 0)
                    *(float2*)&g_h1first[(size_t)row * HH + col] = make_float2(hv[0], hv[1]);
                if (s == TT - 1) {
                    float* hf = LAYER ? g_h1fin : g_h0fin;
                    float* cf = LAYER ? g_c1fin : g_c0fin;
                    *(float2*)&hf[(size_t)row * HH + col] = make_float2(hv[0], hv[1]);
                    *(float2*)&cf[(size_t)row * HH + col] =
                        make_float2(c_reg[mi][rh][0], c_reg[mi][rh][1]);
                }
            }
        __syncthreads();
        if (tid == 0) rel_add(LAYER ? &g_flag1[s * 4 + m] : &g_flag0[s * 4 + m]);
    }
}

__global__ __launch_bounds__(256, 2) void lstm_persistent(
    const float* __restrict__ bih0, const float* __restrict__ bhh0,
    const float* __restrict__ bih1, const float* __restrict__ bhh1) {
    extern __shared__ char smraw[];
    __shared__ float bias_s[CTA_N];
    if (blockIdx.x < 128)
        lstm_run<HH, 1>(blockIdx.x, smraw, bias_s, bih1, bhh1);
    else
        lstm_run<FF, 0>(blockIdx.x - 128, smraw, bias_s, bih0, bhh0);
}

// ---------------- head + output packing ----------------
__global__ void linear_kernel(const float* __restrict__ W_lin,
                              const float* __restrict__ b_lin,
                              float* __restrict__ y) {
    __shared__ float hrow[HH];
    const int b = blockIdx.x;
    for (int i = threadIdx.x; i < HH; i += blockDim.x)
        hrow[i] = g_h1first[(size_t)b * HH + i];
    __syncthreads();
    const int f = threadIdx.x;
    float acc = b_lin[f];
    const float* wv = &W_lin[(size_t)f * HH];
#pragma unroll 4
    for (int k = 0; k < HH; k++) acc += hrow[k] * wv[k];
    y[(size_t)b * FF + f] = acc;
}

__global__ void write_states_kernel(float* __restrict__ out) {
    int i = blockIdx.x * blockDim.x + threadIdx.x;
    if (i >= BB * HH) return;
    const int YO = BB * FF;
    out[YO + i]               = g_h0fin[i];
    out[YO + BB * HH + i]     = g_h1fin[i];
    out[YO + 2 * BB * HH + i] = g_c0fin[i];
    out[YO + 3 * BB * HH + i] = g_c1fin[i];
}

extern "C" void kernel_launch(void* const* d_in, const int* in_sizes, int n_in,
                              void* d_out, int out_size) {
    (void)in_sizes; (void)n_in; (void)out_size;
    const float* x     = (const float*)d_in[0];
    const float* W_ih0 = (const float*)d_in[1];
    const float* W_hh0 = (const float*)d_in[2];
    const float* b_ih0 = (const float*)d_in[3];
    const float* b_hh0 = (const float*)d_in[4];
    const float* W_ih1 = (const float*)d_in[5];
    const float* W_hh1 = (const float*)d_in[6];
    const float* b_ih1 = (const float*)d_in[7];
    const float* b_hh1 = (const float*)d_in[8];
    const float* W_lin = (const float*)d_in[9];
    const float* b_lin = (const float*)d_in[10];
    float* out = (float*)d_out;

    cudaFuncSetAttribute(lstm_persistent,
                         cudaFuncAttributeMaxDynamicSharedMemorySize, SMEM_BYTES);

    prep_all<<<(PREP_TOTAL + 255) / 256, 256>>>(x, W_ih0, W_hh0, W_ih1, W_hh1);
    lstm_persistent<<<256, 256, SMEM_BYTES>>>(b_ih0, b_hh0, b_ih1, b_hh1);
    linear_kernel<<<BB, FF>>>(W_lin, b_lin, out);
    write_states_kernel<<<(BB * HH + 255) / 256, 256>>>(out);
}

// round 8
// speedup vs baseline: 7.6915x; 1.0296x over previous
#include <cuda_runtime.h>
#include <cuda_fp16.h>
#include <math.h>
#include <stdint.h>

// ---------------- problem constants ----------------
#define TT 256
#define BB 256
#define FF 128
#define HH 1024

// ---------------- tiling ----------------
#define KCH     64                         // K halves per chunk
#define CTA_M   64
#define CTA_N   128
#define ROWB    144                        // 72 halves per row
#define A_BYTES (CTA_M * ROWB)             // 9216
#define W_BYTES (CTA_N * ROWB)             // 18432
#define STAGE_BYTES (A_BYTES + W_BYTES)    // 27648
#define SMEM_BYTES  (4 * STAGE_BYTES)      // 110592

// ---------------- persistent device state ----------------
__device__ __half g_h0h[3][BB * HH];       // triple-buffered h0
__device__ __half g_h1h[2][BB * HH];
__device__ __half g_xh[TT * BB * FF];
__device__ __half g_Wih0h[4 * HH * FF];
__device__ __half g_Whh0h[4 * HH * HH];
__device__ __half g_Wih1h[4 * HH * HH];
__device__ __half g_Whh1h[4 * HH * HH];
__device__ float  g_h0fin[BB * HH];
__device__ float  g_h1fin[BB * HH];
__device__ float  g_c0fin[BB * HH];
__device__ float  g_c1fin[BB * HH];
__device__ float  g_h1first[BB * HH];
__device__ uint32_t g_flag0[TT * 4];   // layer0 step done (per m group)
__device__ uint32_t g_flag1[TT * 4];   // layer1 step done
__device__ uint32_t g_cons[TT * 4];    // layer1 consumed h0(s+1)

// ---------------- helpers ----------------
__device__ __forceinline__ uint32_t s2u(const void* p) {
    uint32_t a;
    asm("{ .reg .u64 t; cvta.to.shared.u64 t, %1; cvt.u32.u64 %0, t; }"
        : "=r"(a) : "l"(p));
    return a;
}

__device__ __forceinline__ void cp16(uint32_t s, const void* g) {
    asm volatile("cp.async.cg.shared.global [%0], [%1], 16;" :: "r"(s), "l"(g));
}
#define CP_COMMIT() asm volatile("cp.async.commit_group;" ::: "memory")
#define CP_WAIT(N)  asm volatile("cp.async.wait_group %0;" :: "n"(N) : "memory")

__device__ __forceinline__ void ldsm4(uint32_t* r, uint32_t addr) {
    asm volatile("ldmatrix.sync.aligned.m8n8.x4.shared.b16 {%0,%1,%2,%3}, [%4];"
        : "=r"(r[0]), "=r"(r[1]), "=r"(r[2]), "=r"(r[3]) : "r"(addr));
}

__device__ __forceinline__ void mma16(float* c, const uint32_t* a, uint32_t b0, uint32_t b1) {
    asm volatile(
        "mma.sync.aligned.m16n8k16.row.col.f32.f16.f16.f32 "
        "{%0,%1,%2,%3}, {%4,%5,%6,%7}, {%8,%9}, {%0,%1,%2,%3};"
        : "+f"(c[0]), "+f"(c[1]), "+f"(c[2]), "+f"(c[3])
        : "r"(a[0]), "r"(a[1]), "r"(a[2]), "r"(a[3]), "r"(b0), "r"(b1));
}

__device__ __forceinline__ void spin_ge(const uint32_t* p, uint32_t tgt) {
    uint32_t v;
    while (true) {
        asm volatile("ld.acquire.gpu.global.u32 %0, [%1];" : "=r"(v) : "l"(p) : "memory");
        if (v >= tgt) break;
        __nanosleep(32);
    }
}

__device__ __forceinline__ void rel_add(uint32_t* p) {
    asm volatile("red.release.gpu.global.add.u32 [%0], 1;" :: "l"(p) : "memory");
}

__device__ __forceinline__ float sigmoidf_(float x) { return 1.0f / (1.0f + expf(-x)); }

// ---------------- one-shot prep: fp16 conversions + state/flag zeroing ----------------
#define N_X   (TT * BB * FF)
#define N_WI0 (4 * HH * FF)
#define N_WHH (4 * HH * HH)
#define N_Z   (BB * HH)
#define PREP_TOTAL (N_X + N_WI0 + 3 * N_WHH + 2 * N_Z + 3 * TT * 4)

__global__ void prep_all(const float* __restrict__ x,
                         const float* __restrict__ wi0, const float* __restrict__ wh0,
                         const float* __restrict__ wi1, const float* __restrict__ wh1) {
    long long i = (long long)blockIdx.x * blockDim.x + threadIdx.x;
    if (i >= PREP_TOTAL) return;
    if (i < N_X) { g_xh[i] = __float2half_rn(x[i]); return; }
    i -= N_X;
    if (i < N_WI0) { g_Wih0h[i] = __float2half_rn(wi0[i]); return; }
    i -= N_WI0;
    if (i < N_WHH) { g_Whh0h[i] = __float2half_rn(wh0[i]); return; }
    i -= N_WHH;
    if (i < N_WHH) { g_Wih1h[i] = __float2half_rn(wi1[i]); return; }
    i -= N_WHH;
    if (i < N_WHH) { g_Whh1h[i] = __float2half_rn(wh1[i]); return; }
    i -= N_WHH;
    if (i < N_Z) { g_h0h[0][i] = __float2half(0.0f); return; }
    i -= N_Z;
    if (i < N_Z) { g_h1h[0][i] = __float2half(0.0f); return; }
    i -= N_Z;
    if (i < TT * 4)     { g_flag0[i] = 0; return; }
    i -= TT * 4;
    if (i < TT * 4)     { g_flag1[i] = 0; return; }
    i -= TT * 4;
    g_cons[i] = 0;
}

// ---------------- split chunk loaders (256 threads) ----------------
__device__ __forceinline__ void loadA(uint32_t dstA, int tid,
                                      const __half* __restrict__ aSrc, int ald) {
#pragma unroll
    for (int i = 0; i < 2; i++) {            // 64 rows x 8 segs
        int q = tid + i * 256;
        int row = q >> 3, seg = q & 7;
        cp16(dstA + row * ROWB + seg * 16, aSrc + (size_t)row * ald + seg * 8);
    }
}

__device__ __forceinline__ void loadW(uint32_t dstW, int tid,
                                      const __half* __restrict__ wSrc, int wld, int j0) {
#pragma unroll
    for (int i = 0; i < 4; i++) {            // 128 rows x 8 segs
        int q = tid + i * 256;
        int row = q >> 3, seg = q & 7;
        int g = row >> 5, u = row & 31;
        cp16(dstW + row * ROWB + seg * 16,
             wSrc + (size_t)(g * HH + j0 + u) * wld + seg * 8);
    }
}

// ---------------- persistent per-CTA loop ----------------
// bid 0..127: m = bid&3 (batch 64-tile), nt = bid>>2 (32-unit tile).
// 8 warps = 2(m) x 4(n); warp wn covers units [8wn,8wn+8) for ALL 4 gates so
// the cell update is thread-local and c stays in registers across all steps.
template <int K_IN, int LAYER>
__device__ __forceinline__ void lstm_run(int bid, char* smraw, float* bias_s,
                                         const float* __restrict__ b_ih,
                                         const float* __restrict__ b_hh) {
    constexpr int NC    = (K_IN + HH) / KCH;     // 32 (L1) / 18 (L0)
    constexpr int SPLIT = K_IN / KCH;            // 16 (L1) / 2  (L0)

    const int tid  = threadIdx.x;
    const int w    = tid >> 5;
    const int lane = tid & 31;
    const int wm   = w & 1;
    const int wn   = w >> 1;
    const int r4   = lane >> 2, cl = lane & 3;
    const int m    = bid & 3;
    const int nt   = bid >> 2;
    const int b0   = m * CTA_M;
    const int j0   = nt * 32;

    const uint32_t smb = s2u(smraw);
    const __half* Wih = LAYER ? g_Wih1h : g_Wih0h;
    const __half* Whh = LAYER ? g_Whh1h : g_Whh0h;

    if (tid < CTA_N) {
        int g = tid >> 5, u = tid & 31;
        bias_s[tid] = b_ih[g * HH + j0 + u] + b_hh[g * HH + j0 + u];
    }
    __syncthreads();

    // fragment smem offsets (within a stage buffer)
    const int arow = (lane & 7) + ((lane >> 3) & 1) * 8;
    const int aseg = (lane >> 4) & 1;
    const uint32_t aoff0 = (uint32_t)((wm * 32 + arow) * ROWB + aseg * 16);
    const uint32_t aoff1 = (uint32_t)((wm * 32 + 16 + arow) * ROWB + aseg * 16);
    const uint32_t boffA = (uint32_t)((((lane >> 4) & 1) * 32 + wn * 8 + (lane & 7)) * ROWB
                                      + ((lane >> 3) & 1) * 16);
    const uint32_t boffB = boffA + 64u * ROWB;

    float c_reg[2][2][2];
#pragma unroll
    for (int a = 0; a < 2; a++)
#pragma unroll
        for (int b = 0; b < 2; b++)
#pragma unroll
            for (int d = 0; d < 2; d++) c_reg[a][b][d] = 0.0f;

#pragma unroll 1
    for (int s = 0; s < TT; s++) {
        const __half* inP = LAYER ? g_h0h[(s + 1) % 3]
                                  : g_xh + (size_t)s * BB * FF;
        const __half* hP  = LAYER ? g_h1h[s & 1] : g_h0h[s % 3];

        auto wsrc_for = [&](int ch, const __half*& ws, int& wld) {
            if (ch < SPLIT) { ws = Wih + ch * KCH; wld = K_IN; }
            else            { ws = Whh + (ch - SPLIT) * KCH; wld = HH; }
        };
        auto asrc_for = [&](int ch, const __half*& as, int& ald) {
            if (ch < SPLIT) { as = inP + (size_t)b0 * K_IN + ch * KCH; ald = K_IN; }
            else            { as = hP + (size_t)b0 * HH + (ch - SPLIT) * KCH; ald = HH; }
        };

        // ---- prologue: issue flag-independent W (and x) loads BEFORE spins ----
#pragma unroll
        for (int st = 0; st < 3; st++) {
            const __half* ws; int wld;
            wsrc_for(st, ws, wld);
            loadW(smb + st * STAGE_BYTES + A_BYTES, tid, ws, wld, j0);
        }

        if (LAYER == 0) {
            // x chunks (0,1) are always ready — issue before the h0(s) gate
            const __half* as; int ald;
            asrc_for(0, as, ald);
            loadA(smb + 0 * STAGE_BYTES, tid, as, ald);
            CP_COMMIT();                                   // group0 = {W0,W1,W2,A0}
            asrc_for(1, as, ald);
            loadA(smb + 1 * STAGE_BYTES, tid, as, ald);
            CP_COMMIT();                                   // group1 = {A1}
            if (s > 0) {
                if (tid == 0) spin_ge(&g_flag0[(s - 1) * 4 + m], 32);
                __syncthreads();
            }
            asrc_for(2, as, ald);                          // h0(s) chunk
            loadA(smb + 2 * STAGE_BYTES, tid, as, ald);
            CP_COMMIT();                                   // group2 = {A2}
        } else {
            // layer1: h0(s+1) must be complete before the A loads
            if (tid == 0) spin_ge(&g_flag0[s * 4 + m], 32);
            __syncthreads();
#pragma unroll
            for (int st = 0; st < 3; st++) {
                const __half* as; int ald;
                asrc_for(st, as, ald);
                loadA(smb + st * STAGE_BYTES, tid, as, ald);
                CP_COMMIT();                               // group0={W0..W2,A0}, g1={A1}, g2={A2}
            }
        }

        float acc[2][4][4];
#pragma unroll
        for (int mi = 0; mi < 2; mi++)
#pragma unroll
            for (int g = 0; g < 4; g++)
#pragma unroll
                for (int q = 0; q < 4; q++) acc[mi][g][q] = 0.0f;

#pragma unroll 1
        for (int ch = 0; ch < NC; ch++) {
            if (ch >= NC - 1)      { CP_WAIT(0); }
            else if (ch == NC - 2) { CP_WAIT(1); }
            else                   { CP_WAIT(2); }
            __syncthreads();

            if (ch + 3 < NC) {
                int buf = (ch + 3) & 3;
                // W first — no flag dependency, overlaps the spin below
                const __half* ws; int wld;
                wsrc_for(ch + 3, ws, wld);
                loadW(smb + buf * STAGE_BYTES + A_BYTES, tid, ws, wld, j0);

                // layer1: gate h1(s) reads just before the first h1 chunk's A load
                if (LAYER == 1 && s > 0 && ch == SPLIT - 3) {
                    if (tid == 0) spin_ge(&g_flag1[(s - 1) * 4 + m], 32);
                    __syncthreads();
                }

                const __half* as; int ald;
                asrc_for(ch + 3, as, ald);
                loadA(smb + buf * STAGE_BYTES, tid, as, ald);
                CP_COMMIT();
            }

            const uint32_t aBase = smb + (ch & 3) * STAGE_BYTES;
            const uint32_t wBase = aBase + A_BYTES;

#pragma unroll
            for (int ks = 0; ks < 4; ks++) {
                uint32_t a0[4], a1[4], bA[4], bB[4];
                ldsm4(a0, aBase + aoff0 + ks * 32);
                ldsm4(a1, aBase + aoff1 + ks * 32);
                ldsm4(bA, wBase + boffA + ks * 32);
                ldsm4(bB, wBase + boffB + ks * 32);
                mma16(acc[0][0], a0, bA[0], bA[1]);
                mma16(acc[1][0], a1, bA[0], bA[1]);
                mma16(acc[0][1], a0, bA[2], bA[3]);
                mma16(acc[1][1], a1, bA[2], bA[3]);
                mma16(acc[0][2], a0, bB[0], bB[1]);
                mma16(acc[1][2], a1, bB[0], bB[1]);
                mma16(acc[0][3], a0, bB[2], bB[3]);
                mma16(acc[1][3], a1, bB[2], bB[3]);
            }
        }

        __syncthreads();
        // layer1: signal h0(s+1) fully consumed (all CTA's global reads landed)
        if (LAYER == 1 && tid == 0) rel_add(&g_cons[s * 4 + m]);

        // ---- epilogue: compute gates FIRST (before any WAR spin) ----
        float hv_all[2][2][2];
#pragma unroll
        for (int mi = 0; mi < 2; mi++)
#pragma unroll
            for (int rh = 0; rh < 2; rh++)
#pragma unroll
                for (int du = 0; du < 2; du++) {
                    const int q = rh * 2 + du;
                    const int ul = wn * 8 + 2 * cl + du;
                    float iv = acc[mi][0][q] + bias_s[ul];
                    float fv = acc[mi][1][q] + bias_s[32 + ul];
                    float gv = acc[mi][2][q] + bias_s[64 + ul];
                    float ov = acc[mi][3][q] + bias_s[96 + ul];
                    float cn = sigmoidf_(fv) * c_reg[mi][rh][du]
                             + sigmoidf_(iv) * tanhf(gv);
                    c_reg[mi][rh][du] = cn;
                    hv_all[mi][rh][du] = sigmoidf_(ov) * tanhf(cn);
                }

        // layer0 WAR: before overwriting h0 slot (s+1)%3 (= h0(s-2)), wait
        // until layer1 step s-3 consumed it (triple buffer -> 3 steps slack)
        if (LAYER == 0 && s >= 3) {
            if (tid == 0) spin_ge(&g_cons[(s - 3) * 4 + m], 32);
            __syncthreads();
        }

        __half* hOut = LAYER ? g_h1h[(s + 1) & 1] : g_h0h[(s + 1) % 3];
#pragma unroll
        for (int mi = 0; mi < 2; mi++)
#pragma unroll
            for (int rh = 0; rh < 2; rh++) {
                const int row = b0 + wm * 32 + mi * 16 + r4 + rh * 8;
                const int col = j0 + wn * 8 + 2 * cl;
                *(__half2*)&hOut[(size_t)row * HH + col] =
                    __floats2half2_rn(hv_all[mi][rh][0], hv_all[mi][rh][1]);
                if (LAYER == 1 && s == 0)
                    *(float2*)&g_h1first[(size_t)row * HH + col] =
                        make_float2(hv_all[mi][rh][0], hv_all[mi][rh][1]);
                if (s == TT - 1) {
                    float* hf = LAYER ? g_h1fin : g_h0fin;
                    float* cf = LAYER ? g_c1fin : g_c0fin;
                    *(float2*)&hf[(size_t)row * HH + col] =
                        make_float2(hv_all[mi][rh][0], hv_all[mi][rh][1]);
                    *(float2*)&cf[(size_t)row * HH + col] =
                        make_float2(c_reg[mi][rh][0], c_reg[mi][rh][1]);
                }
            }
        __syncthreads();
        if (tid == 0) rel_add(LAYER ? &g_flag1[s * 4 + m] : &g_flag0[s * 4 + m]);
    }
}

__global__ __launch_bounds__(256, 2) void lstm_persistent(
    const float* __restrict__ bih0, const float* __restrict__ bhh0,
    const float* __restrict__ bih1, const float* __restrict__ bhh1) {
    extern __shared__ char smraw[];
    __shared__ float bias_s[CTA_N];
    if (blockIdx.x < 128)
        lstm_run<HH, 1>(blockIdx.x, smraw, bias_s, bih1, bhh1);
    else
        lstm_run<FF, 0>(blockIdx.x - 128, smraw, bias_s, bih0, bhh0);
}

// ---------------- head + output packing ----------------
__global__ void linear_kernel(const float* __restrict__ W_lin,
                              const float* __restrict__ b_lin,
                              float* __restrict__ y) {
    __shared__ float hrow[HH];
    const int b = blockIdx.x;
    for (int i = threadIdx.x; i < HH; i += blockDim.x)
        hrow[i] = g_h1first[(size_t)b * HH + i];
    __syncthreads();
    const int f = threadIdx.x;
    float acc = b_lin[f];
    const float* wv = &W_lin[(size_t)f * HH];
#pragma unroll 4
    for (int k = 0; k < HH; k++) acc += hrow[k] * wv[k];
    y[(size_t)b * FF + f] = acc;
}

__global__ void write_states_kernel(float* __restrict__ out) {
    int i = blockIdx.x * blockDim.x + threadIdx.x;
    if (i >= BB * HH) return;
    const int YO = BB * FF;
    out[YO + i]               = g_h0fin[i];
    out[YO + BB * HH + i]     = g_h1fin[i];
    out[YO + 2 * BB * HH + i] = g_c0fin[i];
    out[YO + 3 * BB * HH + i] = g_c1fin[i];
}

extern "C" void kernel_launch(void* const* d_in, const int* in_sizes, int n_in,
                              void* d_out, int out_size) {
    (void)in_sizes; (void)n_in; (void)out_size;
    const float* x     = (const float*)d_in[0];
    const float* W_ih0 = (const float*)d_in[1];
    const float* W_hh0 = (const float*)d_in[2];
    const float* b_ih0 = (const float*)d_in[3];
    const float* b_hh0 = (const float*)d_in[4];
    const float* W_ih1 = (const float*)d_in[5];
    const float* W_hh1 = (const float*)d_in[6];
    const float* b_ih1 = (const float*)d_in[7];
    const float* b_hh1 = (const float*)d_in[8];
    const float* W_lin = (const float*)d_in[9];
    const float* b_lin = (const float*)d_in[10];
    float* out = (float*)d_out;

    cudaFuncSetAttribute(lstm_persistent,
                         cudaFuncAttributeMaxDynamicSharedMemorySize, SMEM_BYTES);

    prep_all<<<(PREP_TOTAL + 255) / 256, 256>>>(x, W_ih0, W_hh0, W_ih1, W_hh1);
    lstm_persistent<<<256, 256, SMEM_BYTES>>>(b_ih0, b_hh0, b_ih1, b_hh1);
    linear_kernel<<<BB, FF>>>(W_lin, b_lin, out);
    write_states_kernel<<<(BB * HH + 255) / 256, 256>>>(out);
}